// round 10
// baseline (speedup 1.0000x reference)
#include <cuda_runtime.h>
#include <math.h>

#define BB 256
#define TT 20
#define DD 128
#define HH 256
#define KSZ 256
#define MEMN 20
#define YY 4
#define EPSF 1e-8f
#define NFRM (BB*TT)

// ---------------- device scratch ----------------
__device__ float g_h3[NFRM*512];
__device__ float g_fc1[NFRM*256];
__device__ float g_fc2p[2*NFRM*DD];     // fc2 split-K partials
__device__ float g_z[NFRM*DD];
__device__ float g_gz[NFRM*1024];       // z@Wz^T + lstm_b, (j,gate) interleaved
__device__ float g_heads[BB*768];       // head projections (full K, no partials)
__device__ float g_h[2*BB*HH];          // ping-pong h state
__device__ float g_cst[BB*HH];
__device__ float g_r[BB*KSZ];
__device__ float g_M[BB*MEMN*KSZ];
__device__ float g_Wcat[1024*512];      // rows (j,gate) interleaved, cols [r|h]
__device__ float g_Wz[1024*128];        // rows (j,gate) interleaved
__device__ float g_biasI[1024];         // lstm bias, interleaved
__device__ float g_Whead[768*256];
__device__ float g_w2r[16384];
__device__ float g_w3r[16384];

__device__ __forceinline__ float sigmf(float x){ return 1.f/(1.f+expf(-x)); }

// ---------------- tf32 mma helpers ----------------
__device__ __forceinline__ void mma8(float* c, const unsigned* a, const unsigned* b)
{
    asm volatile(
        "mma.sync.aligned.m16n8k8.row.col.f32.tf32.tf32.f32 "
        "{%0,%1,%2,%3},{%4,%5,%6,%7},{%8,%9},{%0,%1,%2,%3};"
        : "+f"(c[0]), "+f"(c[1]), "+f"(c[2]), "+f"(c[3])
        : "r"(a[0]), "r"(a[1]), "r"(a[2]), "r"(a[3]), "r"(b[0]), "r"(b[1]));
}
__device__ __forceinline__ void split2(float x, unsigned& hi, unsigned& lo)
{
    unsigned h = __float_as_uint(x) & 0xffffe000u;
    hi = h;
    lo = __float_as_uint(x - __uint_as_float(h));
}
__device__ __forceinline__ void cpasync16(unsigned dst, const void* src)
{
    asm volatile("cp.async.cg.shared.global [%0], [%1], 16;\n" :: "r"(dst), "l"(src));
}

// ---------------- fused conv encoder (tensor-core conv2/conv3) ----------------
#define S_H1 1156
#define S_H2 13144
#define S_C3 16844
#define CONVF_SMEM_FLOATS 17900

__global__ void __launch_bounds__(256, 2) k_convf(
    const float* __restrict__ x,
    const float* __restrict__ w1, const float* __restrict__ b1,
    const float* __restrict__ w2r, const float* __restrict__ b2,
    const float* __restrict__ w3r, const float* __restrict__ b3)
{
    extern __shared__ float sm[];
    float* s_in = sm;
    float* s_h1 = sm + S_H1;
    float* s_h2 = sm + S_H2;
    float* s_c3 = sm + S_C3;
    const int f = blockIdx.x, tid = threadIdx.x;
    const int lane = tid & 31, warpid = tid >> 5;
    const int g = lane >> 2, tig = lane & 3;

    for (int i = tid; i < S_C3; i += 256) sm[i] = 0.f;
    __syncthreads();
    for (int i = tid; i < 1024; i += 256) {
        int iy = i >> 5, ix = i & 31;
        s_in[(iy+1)*34 + ix + 1] = x[f*1024 + i];
    }
    __syncthreads();

    // ---- conv1 (FFMA), write channel-last ----
    for (int p = tid; p < 512; p += 256) {
        int oc = p >> 4, oy = p & 15;
        float bias = __ldg(b1 + oc);
        float acc[16];
        #pragma unroll
        for (int ox = 0; ox < 16; ox++) acc[ox] = bias;
        #pragma unroll
        for (int kh = 0; kh < 4; kh++) {
            const float* row = s_in + (2*oy+kh)*34;
            const float4 w = __ldg((const float4*)(w1 + oc*16 + kh*4));
            #pragma unroll
            for (int ox = 0; ox < 16; ox++) {
                acc[ox] += row[2*ox]*w.x + row[2*ox+1]*w.y
                         + row[2*ox+2]*w.z + row[2*ox+3]*w.w;
            }
        }
        int cellbase = (oy+1)*18 + 1;
        #pragma unroll
        for (int ox = 0; ox < 16; ox++)
            s_h1[(cellbase + ox)*37 + oc] = fmaxf(acc[ox], 0.f);
    }
    __syncthreads();

    // ---- conv2 (tf32 mma) ----
    {
        const int wm = warpid & 3, wn = warpid >> 2;
        float acc[2][4] = {{0.f,0.f,0.f,0.f},{0.f,0.f,0.f,0.f}};
        int pA = wm*16 + g, pB = pA + 8;
        int oyA = pA >> 3, oxA = pA & 7;
        int oyB = pB >> 3, oxB = pB & 7;
        #pragma unroll 1
        for (int khw = 0; khw < 16; khw++) {
            int kh = khw >> 2, kw = khw & 3;
            const float* hA = s_h1 + ((2*oyA + kh)*18 + 2*oxA + kw)*37;
            const float* hB = s_h1 + ((2*oyB + kh)*18 + 2*oxB + kw)*37;
            #pragma unroll
            for (int ick = 0; ick < 4; ick++) {
                int ic0 = ick*8;
                unsigned ahi[4], alo[4];
                split2(hA[ic0+tig],   ahi[0], alo[0]);
                split2(hB[ic0+tig],   ahi[1], alo[1]);
                split2(hA[ic0+tig+4], ahi[2], alo[2]);
                split2(hB[ic0+tig+4], ahi[3], alo[3]);
                int idx128 = (khw*4 + ick)*2;
                #pragma unroll
                for (int ni = 0; ni < 2; ni++) {
                    int n8i = wn*2 + ni;
                    unsigned bhi[2], blo[2];
                    float b0 = __ldg(w2r + ((idx128+0)*4 + n8i)*32 + lane);
                    float b1v= __ldg(w2r + ((idx128+1)*4 + n8i)*32 + lane);
                    split2(b0,  bhi[0], blo[0]);
                    split2(b1v, bhi[1], blo[1]);
                    mma8(acc[ni], ahi, bhi);
                    mma8(acc[ni], alo, bhi);
                    mma8(acc[ni], ahi, blo);
                }
            }
        }
        int cellA = (oyA+1)*10 + oxA + 1;
        int cellB = (oyB+1)*10 + oxB + 1;
        #pragma unroll
        for (int ni = 0; ni < 2; ni++) {
            int col0 = wn*16 + ni*8 + 2*tig;
            float bb0 = __ldg(b2 + col0), bb1 = __ldg(b2 + col0 + 1);
            s_h2[cellA*37 + col0]     = fmaxf(acc[ni][0] + bb0, 0.f);
            s_h2[cellA*37 + col0 + 1] = fmaxf(acc[ni][1] + bb1, 0.f);
            s_h2[cellB*37 + col0]     = fmaxf(acc[ni][2] + bb0, 0.f);
            s_h2[cellB*37 + col0 + 1] = fmaxf(acc[ni][3] + bb1, 0.f);
        }
    }
    __syncthreads();

    // ---- conv3 (tf32 mma, 2-way K-split across warps) ----
    {
        const int n8i = warpid & 3, khalf = warpid >> 2;
        float acc[4] = {0.f, 0.f, 0.f, 0.f};
        int pA = g, pB = g + 8;
        int oyA = pA >> 2, oxA = pA & 3;
        int oyB = pB >> 2, oxB = pB & 3;
        #pragma unroll 1
        for (int kk = 0; kk < 8; kk++) {
            int khw = khalf*8 + kk;
            int kh = khw >> 2, kw = khw & 3;
            const float* hA = s_h2 + ((2*oyA + kh)*10 + 2*oxA + kw)*37;
            const float* hB = s_h2 + ((2*oyB + kh)*10 + 2*oxB + kw)*37;
            #pragma unroll
            for (int ick = 0; ick < 4; ick++) {
                int ic0 = ick*8;
                unsigned ahi[4], alo[4];
                split2(hA[ic0+tig],   ahi[0], alo[0]);
                split2(hB[ic0+tig],   ahi[1], alo[1]);
                split2(hA[ic0+tig+4], ahi[2], alo[2]);
                split2(hB[ic0+tig+4], ahi[3], alo[3]);
                int idx128 = (khw*4 + ick)*2;
                unsigned bhi[2], blo[2];
                float b0 = __ldg(w3r + ((idx128+0)*4 + n8i)*32 + lane);
                float b1v= __ldg(w3r + ((idx128+1)*4 + n8i)*32 + lane);
                split2(b0,  bhi[0], blo[0]);
                split2(b1v, bhi[1], blo[1]);
                mma8(acc, ahi, bhi);
                mma8(acc, alo, bhi);
                mma8(acc, ahi, blo);
            }
        }
        int col0 = n8i*8 + 2*tig;
        s_c3[(khalf*16 + g)*33 + col0]       = acc[0];
        s_c3[(khalf*16 + g)*33 + col0 + 1]   = acc[1];
        s_c3[(khalf*16 + g+8)*33 + col0]     = acc[2];
        s_c3[(khalf*16 + g+8)*33 + col0 + 1] = acc[3];
    }
    __syncthreads();
    for (int idx = tid; idx < 512; idx += 256) {
        int p = idx >> 5, oc = idx & 31;
        float v = s_c3[p*33 + oc] + s_c3[(16+p)*33 + oc] + __ldg(b3 + oc);
        g_h3[f*512 + oc*16 + p] = fmaxf(v, 0.f);
    }
}

// ---------------- chunked 3xTF32 GEMM, 64x128 tile (fc1, K=512) ----------------
__global__ void __launch_bounds__(256) k_tc(
    const float* __restrict__ A, int lda,
    const float* __restrict__ W, int ldw,
    const float* __restrict__ bias,
    float* __restrict__ C, int ldc, int K, int ep)
{
    __shared__ float sA[32][72];
    __shared__ float sW[32][136];

    const int tid = threadIdx.x;
    const int warpid = tid >> 5, lane = tid & 31;
    const int g = lane >> 2, tig = lane & 3;
    const int wm = warpid >> 2, wn = warpid & 3;
    const int mtile = blockIdx.y, ntile = blockIdx.x;

    const int arow0 = tid & 63, akq0 = tid >> 6;
    const int akq1 = akq0 + 4;
    const float* Abase0 = A + (mtile*64 + arow0)*lda + akq0*4;
    const float* Abase1 = A + (mtile*64 + arow0)*lda + akq1*4;

    float acc[2][4][4];
    #pragma unroll
    for (int mi = 0; mi < 2; mi++)
        #pragma unroll
        for (int ni = 0; ni < 4; ni++)
            #pragma unroll
            for (int q = 0; q < 4; q++) acc[mi][ni][q] = 0.f;

    const int nkc = K >> 5;
    float4 pa0 = *(const float4*)(Abase0);
    float4 pa1 = *(const float4*)(Abase1);
    float4 pw[4];
    #pragma unroll
    for (int q = 0; q < 4; q++) {
        int idx = tid + q*256;
        int n = idx & 127, kq = idx >> 7;
        pw[q] = *(const float4*)(W + (ntile*128 + n)*ldw + kq*4);
    }

    for (int kt = 0; kt < nkc; kt++) {
        sA[akq0*4+0][arow0] = pa0.x; sA[akq0*4+1][arow0] = pa0.y;
        sA[akq0*4+2][arow0] = pa0.z; sA[akq0*4+3][arow0] = pa0.w;
        sA[akq1*4+0][arow0] = pa1.x; sA[akq1*4+1][arow0] = pa1.y;
        sA[akq1*4+2][arow0] = pa1.z; sA[akq1*4+3][arow0] = pa1.w;
        #pragma unroll
        for (int q = 0; q < 4; q++) {
            int idx = tid + q*256;
            int n = idx & 127, kq = idx >> 7;
            sW[kq*4+0][n] = pw[q].x; sW[kq*4+1][n] = pw[q].y;
            sW[kq*4+2][n] = pw[q].z; sW[kq*4+3][n] = pw[q].w;
        }
        __syncthreads();

        if (kt + 1 < nkc) {
            int kb = (kt+1) << 5;
            pa0 = *(const float4*)(Abase0 + kb);
            pa1 = *(const float4*)(Abase1 + kb);
            #pragma unroll
            for (int q = 0; q < 4; q++) {
                int idx = tid + q*256;
                int n = idx & 127, kq = idx >> 7;
                pw[q] = *(const float4*)(W + (ntile*128 + n)*ldw + kb + kq*4);
            }
        }

        #pragma unroll
        for (int kk = 0; kk < 4; kk++) {
            const int k0 = kk*8 + tig, k1 = k0 + 4;
            unsigned ahi[2][4], alo[2][4], bhi[4][2], blo[4][2];
            #pragma unroll
            for (int mi = 0; mi < 2; mi++) {
                int r0 = wm*32 + mi*16 + g;
                split2(sA[k0][r0],    ahi[mi][0], alo[mi][0]);
                split2(sA[k0][r0+8],  ahi[mi][1], alo[mi][1]);
                split2(sA[k1][r0],    ahi[mi][2], alo[mi][2]);
                split2(sA[k1][r0+8],  ahi[mi][3], alo[mi][3]);
            }
            #pragma unroll
            for (int ni = 0; ni < 4; ni++) {
                int c0 = wn*32 + ni*8 + g;
                split2(sW[k0][c0], bhi[ni][0], blo[ni][0]);
                split2(sW[k1][c0], bhi[ni][1], blo[ni][1]);
            }
            #pragma unroll
            for (int mi = 0; mi < 2; mi++)
                #pragma unroll
                for (int ni = 0; ni < 4; ni++) {
                    mma8(acc[mi][ni], ahi[mi], bhi[ni]);
                    mma8(acc[mi][ni], alo[mi], bhi[ni]);
                    mma8(acc[mi][ni], ahi[mi], blo[ni]);
                }
        }
        __syncthreads();
    }

    #pragma unroll
    for (int mi = 0; mi < 2; mi++) {
        #pragma unroll
        for (int ni = 0; ni < 4; ni++) {
            int row0 = mtile*64 + wm*32 + mi*16 + g;
            int col0 = ntile*128 + wn*32 + ni*8 + 2*tig;
            float v0 = acc[mi][ni][0], v1 = acc[mi][ni][1];
            float v2 = acc[mi][ni][2], v3 = acc[mi][ni][3];
            if (ep >= 1) {
                float b0 = bias[col0], b1 = bias[col0+1];
                v0 += b0; v1 += b1; v2 += b0; v3 += b1;
            }
            if (ep == 2) {
                v0 = fmaxf(v0, 0.f); v1 = fmaxf(v1, 0.f);
                v2 = fmaxf(v2, 0.f); v3 = fmaxf(v3, 0.f);
            }
            float* p = C + row0*ldc + col0;
            p[0] = v0; p[1] = v1;
            p[8*ldc] = v2; p[8*ldc + 1] = v3;
        }
    }
}

// ---------------- single-stage 3xTF32 GEMM, 64x128 tile (fc2 / Gz) ----------------
#define TCS_SMEM_BYTES ((64*132 + 128*132)*4)

__global__ void __launch_bounds__(256) k_tcs(
    const float* __restrict__ A, int lda,
    const float* __restrict__ W, int ldw,
    const float* __restrict__ bias,
    float* __restrict__ C, int ldc,
    int partStride, int ep)
{
    extern __shared__ float smem[];
    float* sA = smem;
    float* sW = smem + 64*132;
    const int tid = threadIdx.x;
    const int warpid = tid >> 5, lane = tid & 31;
    const int g = lane >> 2, tig = lane & 3;
    const int wm = warpid >> 2, wn = warpid & 3;
    const int mtile = blockIdx.y, ntile = blockIdx.x, z = blockIdx.z;
    const int kStart = z*128;
    float* Cp = C + z*partStride;

    #pragma unroll
    for (int q = 0; q < 8; q++) {
        int c = tid + q*256;
        int row = c >> 5, kc = c & 31;
        const float* src = A + (mtile*64 + row)*lda + kStart + kc*4;
        cpasync16((unsigned)__cvta_generic_to_shared(sA + row*132 + kc*4), src);
    }
    #pragma unroll
    for (int q = 0; q < 16; q++) {
        int c = tid + q*256;
        int col = c >> 5, kc = c & 31;
        const float* src = W + (ntile*128 + col)*ldw + kStart + kc*4;
        cpasync16((unsigned)__cvta_generic_to_shared(sW + col*132 + kc*4), src);
    }
    asm volatile("cp.async.commit_group;\n");
    asm volatile("cp.async.wait_group 0;\n");
    __syncthreads();

    float acc[2][4][4];
    #pragma unroll
    for (int mi = 0; mi < 2; mi++)
        #pragma unroll
        for (int ni = 0; ni < 4; ni++)
            #pragma unroll
            for (int q = 0; q < 4; q++) acc[mi][ni][q] = 0.f;

    #pragma unroll 2
    for (int kk = 0; kk < 16; kk++) {
        const int k0 = kk*8 + tig, k1 = k0 + 4;
        unsigned ahi[2][4], alo[2][4], bhi[4][2], blo[4][2];
        #pragma unroll
        for (int mi = 0; mi < 2; mi++) {
            const float* r0 = sA + (wm*32 + mi*16 + g)*132;
            const float* r1 = r0 + 8*132;
            split2(r0[k0], ahi[mi][0], alo[mi][0]);
            split2(r1[k0], ahi[mi][1], alo[mi][1]);
            split2(r0[k1], ahi[mi][2], alo[mi][2]);
            split2(r1[k1], ahi[mi][3], alo[mi][3]);
        }
        #pragma unroll
        for (int ni = 0; ni < 4; ni++) {
            const float* c0 = sW + (wn*32 + ni*8 + g)*132;
            split2(c0[k0], bhi[ni][0], blo[ni][0]);
            split2(c0[k1], bhi[ni][1], blo[ni][1]);
        }
        #pragma unroll
        for (int mi = 0; mi < 2; mi++)
            #pragma unroll
            for (int ni = 0; ni < 4; ni++) {
                mma8(acc[mi][ni], ahi[mi], bhi[ni]);
                mma8(acc[mi][ni], alo[mi], bhi[ni]);
                mma8(acc[mi][ni], ahi[mi], blo[ni]);
            }
    }

    #pragma unroll
    for (int mi = 0; mi < 2; mi++) {
        #pragma unroll
        for (int ni = 0; ni < 4; ni++) {
            int row0 = mtile*64 + wm*32 + mi*16 + g;
            int col0 = ntile*128 + wn*32 + ni*8 + 2*tig;
            float v0 = acc[mi][ni][0], v1 = acc[mi][ni][1];
            float v2 = acc[mi][ni][2], v3 = acc[mi][ni][3];
            if (ep >= 1) {
                float b0 = bias[col0], b1 = bias[col0+1];
                v0 += b0; v1 += b1; v2 += b0; v3 += b1;
            }
            float* p = Cp + row0*ldc + col0;
            p[0] = v0; p[1] = v1;
            p[8*ldc] = v2; p[8*ldc + 1] = v3;
        }
    }
}

// ---------------- chunked 3xTF32 GEMM, 64x64 tile, full K (gates/heads) -------------
// mode 0: A plain. mode 1: A row b = [r(b,:) | h(t)(b,:)] (512 cols).
// fuse 1: gates path — no C write; LSTM epilogue via smem tile (gz pre-biased,
//         cols (j,gate) interleaved). fuse 0: write C, tanh for global col >= 512.
__global__ void __launch_bounds__(256) k_g64(
    const float* __restrict__ A, int lda,
    const float* __restrict__ W, int ldw,
    float* __restrict__ C, int ldc,
    int K, int mode, int fuse, int t)
{
    __shared__ float sA[32][72];
    __shared__ float sW[32][72];
    __shared__ float s_out[64][68];

    const int tid = threadIdx.x;
    const int warpid = tid >> 5, lane = tid & 31;
    const int g = lane >> 2, tig = lane & 3;
    const int wm = warpid & 1, wn = warpid >> 1;   // 2 x 4 warp grid
    const int mtile = blockIdx.y, ntile = blockIdx.x;

    const int arow = tid & 63, akq = tid >> 6;     // akq 0..3

    const float* hcur = g_h + (t & 1)*BB*HH;
    auto ldA = [&](int kbase, int kq) -> float4 {
        int row = mtile*64 + arow;
        int c = kbase + kq*4;
        if (mode == 1) {
            if (c < KSZ) return *(const float4*)(g_r + row*KSZ + c);
            return *(const float4*)(hcur + row*HH + (c - KSZ));
        }
        return *(const float4*)(A + row*lda + c);
    };
    auto ldW = [&](int kbase, int kq) -> float4 {
        return *(const float4*)(W + (ntile*64 + arow)*ldw + kbase + kq*4);
    };

    float acc[2][2][4];
    #pragma unroll
    for (int mi = 0; mi < 2; mi++)
        #pragma unroll
        for (int ni = 0; ni < 2; ni++)
            #pragma unroll
            for (int q = 0; q < 4; q++) acc[mi][ni][q] = 0.f;

    const int nkc = K >> 5;
    float4 pa0 = ldA(0, akq), pa1 = ldA(0, akq + 4);
    float4 pw0 = ldW(0, akq), pw1 = ldW(0, akq + 4);

    for (int kt = 0; kt < nkc; kt++) {
        sA[akq*4+0][arow] = pa0.x; sA[akq*4+1][arow] = pa0.y;
        sA[akq*4+2][arow] = pa0.z; sA[akq*4+3][arow] = pa0.w;
        sA[(akq+4)*4+0][arow] = pa1.x; sA[(akq+4)*4+1][arow] = pa1.y;
        sA[(akq+4)*4+2][arow] = pa1.z; sA[(akq+4)*4+3][arow] = pa1.w;
        sW[akq*4+0][arow] = pw0.x; sW[akq*4+1][arow] = pw0.y;
        sW[akq*4+2][arow] = pw0.z; sW[akq*4+3][arow] = pw0.w;
        sW[(akq+4)*4+0][arow] = pw1.x; sW[(akq+4)*4+1][arow] = pw1.y;
        sW[(akq+4)*4+2][arow] = pw1.z; sW[(akq+4)*4+3][arow] = pw1.w;
        __syncthreads();

        if (kt + 1 < nkc) {
            int kb = (kt+1) << 5;
            pa0 = ldA(kb, akq); pa1 = ldA(kb, akq + 4);
            pw0 = ldW(kb, akq); pw1 = ldW(kb, akq + 4);
        }

        #pragma unroll
        for (int kk = 0; kk < 4; kk++) {
            const int k0 = kk*8 + tig, k1 = k0 + 4;
            unsigned ahi[2][4], alo[2][4], bhi[2][2], blo[2][2];
            #pragma unroll
            for (int mi = 0; mi < 2; mi++) {
                int r0 = wm*32 + mi*16 + g;
                split2(sA[k0][r0],   ahi[mi][0], alo[mi][0]);
                split2(sA[k0][r0+8], ahi[mi][1], alo[mi][1]);
                split2(sA[k1][r0],   ahi[mi][2], alo[mi][2]);
                split2(sA[k1][r0+8], ahi[mi][3], alo[mi][3]);
            }
            #pragma unroll
            for (int ni = 0; ni < 2; ni++) {
                int c0 = wn*16 + ni*8 + g;
                split2(sW[k0][c0], bhi[ni][0], blo[ni][0]);
                split2(sW[k1][c0], bhi[ni][1], blo[ni][1]);
            }
            #pragma unroll
            for (int mi = 0; mi < 2; mi++)
                #pragma unroll
                for (int ni = 0; ni < 2; ni++) {
                    mma8(acc[mi][ni], ahi[mi], bhi[ni]);
                    mma8(acc[mi][ni], alo[mi], bhi[ni]);
                    mma8(acc[mi][ni], ahi[mi], blo[ni]);
                }
        }
        __syncthreads();
    }

    if (!fuse) {
        #pragma unroll
        for (int mi = 0; mi < 2; mi++) {
            #pragma unroll
            for (int ni = 0; ni < 2; ni++) {
                int row0 = mtile*64 + wm*32 + mi*16 + g;
                int col0 = ntile*64 + wn*16 + ni*8 + 2*tig;
                float v0 = acc[mi][ni][0], v1 = acc[mi][ni][1];
                float v2 = acc[mi][ni][2], v3 = acc[mi][ni][3];
                if (col0 >= 512) {
                    v0 = tanhf(v0); v1 = tanhf(v1);
                    v2 = tanhf(v2); v3 = tanhf(v3);
                }
                float* p = C + row0*ldc + col0;
                p[0] = v0; p[1] = v1;
                p[8*ldc] = v2; p[8*ldc + 1] = v3;
            }
        }
    } else {
        // LSTM epilogue: stage accumulators, then (b,j) quads
        #pragma unroll
        for (int mi = 0; mi < 2; mi++)
            #pragma unroll
            for (int ni = 0; ni < 2; ni++) {
                int r0 = wm*32 + mi*16 + g;
                int c0 = wn*16 + ni*8 + 2*tig;
                s_out[r0][c0]       = acc[mi][ni][0];
                s_out[r0][c0+1]     = acc[mi][ni][1];
                s_out[r0+8][c0]     = acc[mi][ni][2];
                s_out[r0+8][c0+1]   = acc[mi][ni][3];
            }
        __syncthreads();
        float* hn = g_h + ((t + 1) & 1)*BB*HH;
        #pragma unroll
        for (int q = 0; q < 4; q++) {
            int p = tid + q*256;          // 1024 (b_local, j_local) pairs
            int bl = p >> 4, jl = p & 15;
            int b = mtile*64 + bl;
            int j = ntile*16 + jl;
            float4 gs = *(const float4*)(g_gz + (b*TT + t)*1024 + j*4);
            gs.x += s_out[bl][jl*4+0];
            gs.y += s_out[bl][jl*4+1];
            gs.z += s_out[bl][jl*4+2];
            gs.w += s_out[bl][jl*4+3];
            float c = g_cst[b*HH + j];
            float cn = sigmf(gs.y)*c + sigmf(gs.x)*tanhf(gs.z);
            float hv = sigmf(gs.w)*tanhf(cn);
            g_cst[b*HH + j] = cn;
            hn[b*HH + j] = hv;
        }
    }
}

// ---------------- context norm over time, fused fc2 combine + bias + relu ------------
__global__ void k_ctxnorm(const float* __restrict__ fc2b,
                          const float* __restrict__ gamma, const float* __restrict__ beta)
{
    int b = blockIdx.x, d = threadIdx.x;
    float bias = fc2b[d];
    float v[TT];
    float s = 0.f, s2 = 0.f;
    #pragma unroll
    for (int t = 0; t < TT; t++) {
        int idx = (b*TT+t)*DD + d;
        v[t] = fmaxf(g_fc2p[idx] + g_fc2p[NFRM*DD + idx] + bias, 0.f);
        s += v[t]; s2 += v[t]*v[t];
    }
    float mu  = s / TT;
    float var = (s2 - TT*mu*mu) / (TT - 1);
    float inv = 1.f / sqrtf(var + EPSF);
    float ga = gamma[d], be = beta[d];
    #pragma unroll
    for (int t = 0; t < TT; t++)
        g_z[(b*TT+t)*DD + d] = (v[t] - mu)*inv*ga + be;
}

// ---------------- setup ----------------
__global__ void k_setup(const float* __restrict__ mem0,
                        const float* __restrict__ wi, const float* __restrict__ wh,
                        const float* __restrict__ lb,
                        const float* __restrict__ wk, const float* __restrict__ wwk,
                        const float* __restrict__ wv,
                        const float* __restrict__ w2, const float* __restrict__ w3,
                        float* __restrict__ out, int out_size)
{
    int i = blockIdx.x*256 + threadIdx.x;
    if (i < BB*MEMN*KSZ) g_M[i] = mem0[i % (MEMN*KSZ)];
    if (i < 1024*512) {
        int rp = i >> 9, c = i & 511;
        int j = rp >> 2, gt = rp & 3;
        int orig = gt*256 + j;
        g_Wcat[i] = (c < 256) ? wi[orig*384 + 128 + c] : wh[orig*256 + (c-256)];
    }
    if (i < 1024*128) {
        int rp = i >> 7, c = i & 127;
        int j = rp >> 2, gt = rp & 3;
        g_Wz[i] = wi[(gt*256 + j)*384 + c];
    }
    if (i < 1024) {
        int j = i >> 2, gt = i & 3;
        g_biasI[i] = lb[gt*256 + j];
    }
    if (i < 768*256) {
        int n = i >> 8;
        g_Whead[i] = (n < 256) ? wk[i] : ((n < 512) ? wwk[i - 256*256] : wv[i - 512*256]);
    }
    if (i < 16384) {
        int lane = i & 31;
        int j = i >> 5;
        int n8i = j & 3; j >>= 2;
        int half = j & 1; j >>= 1;
        int ick = j & 3;
        int khw = j >> 2;
        int n = n8i*8 + (lane >> 2);
        int kic = ick*8 + (lane & 3) + half*4;
        g_w2r[i] = w2[n*512 + kic*16 + khw];
        g_w3r[i] = w3[n*512 + kic*16 + khw];
    }
    if (i < 2*BB*HH) g_h[i] = 0.f;
    if (i < BB*HH) g_cst[i] = 0.f;
    if (i < BB*KSZ) g_r[i] = 0.f;
    if (i < out_size) out[i] = 0.f;
}

// ---------------- per-step: memory read/write + (last step) output ----------------
__global__ void __launch_bounds__(256) k_mem(int t, const float* __restrict__ wo,
                                             const float* __restrict__ wob,
                                             const float* __restrict__ hbuf,
                                             float* __restrict__ out, int out_size)
{
    __shared__ float s_kr[256], s_kw[256], s_rnew[256];
    __shared__ float s_simr[MEMN], s_simw[MEMN];
    __shared__ float s_wr[4], s_ws[4];
    __shared__ int   s_ir[4], s_iw[4];
    __shared__ float s_red[16];
    __shared__ float s_nrm[2];
    __shared__ float s_y[4];

    int b = blockIdx.x, tid = threadIdx.x;
    int lane = tid & 31, wid = tid >> 5;

    const float* hd = g_heads + b*768;
    float kr = hd[tid];
    float kw = hd[256 + tid];
    float vv = hd[512 + tid];   // already tanh'd in k_g64 epilogue
    s_kr[tid] = kr;
    s_kw[tid] = kw;

    float pr = kr*kr, pw = kw*kw;
    #pragma unroll
    for (int o = 16; o > 0; o >>= 1) {
        pr += __shfl_xor_sync(0xffffffffu, pr, o);
        pw += __shfl_xor_sync(0xffffffffu, pw, o);
    }
    if (lane == 0) { s_red[wid] = pr; s_red[8 + wid] = pw; }
    __syncthreads();
    if (tid == 0) {
        float sr = 0.f, sw = 0.f;
        #pragma unroll
        for (int w = 0; w < 8; w++) { sr += s_red[w]; sw += s_red[8 + w]; }
        s_nrm[0] = 1.f / (sqrtf(sr) + EPSF);
        s_nrm[1] = 1.f / (sqrtf(sw) + EPSF);
    }
    __syncthreads();

    for (int n = wid; n < MEMN; n += 8) {
        const float* Mr = g_M + (b*MEMN + n)*KSZ;
        float dr = 0.f, dw = 0.f, nn = 0.f;
        #pragma unroll
        for (int d0 = 0; d0 < KSZ; d0 += 32) {
            float m = Mr[d0 + lane];
            dr += s_kr[d0 + lane]*m;
            dw += s_kw[d0 + lane]*m;
            nn += m*m;
        }
        #pragma unroll
        for (int o = 16; o > 0; o >>= 1) {
            dr += __shfl_xor_sync(0xffffffffu, dr, o);
            dw += __shfl_xor_sync(0xffffffffu, dw, o);
            nn += __shfl_xor_sync(0xffffffffu, nn, o);
        }
        if (lane == 0) {
            float mi = 1.f / (sqrtf(nn) + EPSF);
            s_simr[n] = dr * s_nrm[0] * mi;
            s_simw[n] = dw * s_nrm[1] * mi;
        }
    }
    __syncthreads();

    if (tid < 2) {
        const float* sims = tid ? s_simw : s_simr;
        float* wout = tid ? s_ws : s_wr;
        int*   iout = tid ? s_iw : s_ir;
        unsigned used = 0;
        float vals[4];
        #pragma unroll
        for (int k = 0; k < 4; k++) {
            float best = -1e30f; int bi = 0;
            for (int n = 0; n < MEMN; n++) {
                if (!((used >> n) & 1u) && sims[n] > best) { best = sims[n]; bi = n; }
            }
            used |= 1u << bi;
            iout[k] = bi; vals[k] = best;
        }
        float mx = vals[0], ssum = 0.f, e[4];
        #pragma unroll
        for (int k = 0; k < 4; k++) { e[k] = expf(vals[k] - mx); ssum += e[k]; }
        #pragma unroll
        for (int k = 0; k < 4; k++) wout[k] = e[k] / ssum;
    }
    __syncthreads();

    float r = 0.f;
    #pragma unroll
    for (int k = 0; k < 4; k++)
        r += s_wr[k] * g_M[(b*MEMN + s_ir[k])*KSZ + tid];
    g_r[b*KSZ + tid] = r;
    s_rnew[tid] = r;

    #pragma unroll
    for (int k = 0; k < 4; k++)
        g_M[(b*MEMN + s_iw[k])*KSZ + tid] += s_ws[k] * vv;

    if (t == TT - 1) {
        __syncthreads();
        if (wid < 4) {
            const float* wrow = wo + wid*512;
            float p = 0.f;
            for (int j = lane; j < 256; j += 32) p += wrow[j]       * hbuf[b*HH + j];
            for (int j = lane; j < 256; j += 32) p += wrow[256 + j] * s_rnew[j];
            #pragma unroll
            for (int o = 16; o > 0; o >>= 1) p += __shfl_xor_sync(0xffffffffu, p, o);
            if (lane == 0) s_y[wid] = p + wob[wid];
        }
        __syncthreads();
        if (tid < 4 && (b*4 + tid) < out_size) out[b*4 + tid] = s_y[tid];
        if (tid == 0 && out_size >= BB*YY + BB) {
            int am = 0; float bv = s_y[0];
            #pragma unroll
            for (int o = 1; o < 4; o++) if (s_y[o] > bv) { bv = s_y[o]; am = o; }
            out[BB*YY + b] = (float)am;
        }
    }
}

// ---------------- launch ----------------
extern "C" void kernel_launch(void* const* d_in, const int* in_sizes, int n_in,
                              void* d_out, int out_size)
{
    const float* x    = (const float*)d_in[0];
    const float* c1w  = (const float*)d_in[1];
    const float* c1b  = (const float*)d_in[2];
    const float* c2w  = (const float*)d_in[3];
    const float* c2b  = (const float*)d_in[4];
    const float* c3w  = (const float*)d_in[5];
    const float* c3b  = (const float*)d_in[6];
    const float* fc1w = (const float*)d_in[7];
    const float* fc1b = (const float*)d_in[8];
    const float* fc2w = (const float*)d_in[9];
    const float* fc2b = (const float*)d_in[10];
    const float* gamma= (const float*)d_in[11];
    const float* beta = (const float*)d_in[12];
    const float* lwi  = (const float*)d_in[13];
    const float* lwh  = (const float*)d_in[14];
    const float* lb   = (const float*)d_in[15];
    const float* wk   = (const float*)d_in[16];
    const float* wwk  = (const float*)d_in[17];
    const float* wv   = (const float*)d_in[18];
    const float* wo   = (const float*)d_in[19];
    const float* wob  = (const float*)d_in[20];
    const float* mem0 = (const float*)d_in[21];
    float* out = (float*)d_out;

    cudaFuncSetAttribute(k_convf, cudaFuncAttributeMaxDynamicSharedMemorySize,
                         CONVF_SMEM_FLOATS * 4);
    cudaFuncSetAttribute(k_tcs, cudaFuncAttributeMaxDynamicSharedMemorySize,
                         TCS_SMEM_BYTES);

    float *p_h3, *p_fc1, *p_fc2p, *p_z, *p_gz, *p_heads, *p_hbuf;
    float *p_wcat, *p_wz, *p_whead, *p_w2r, *p_w3r, *p_biasI;
    cudaGetSymbolAddress((void**)&p_h3,    g_h3);
    cudaGetSymbolAddress((void**)&p_fc1,   g_fc1);
    cudaGetSymbolAddress((void**)&p_fc2p,  g_fc2p);
    cudaGetSymbolAddress((void**)&p_z,     g_z);
    cudaGetSymbolAddress((void**)&p_gz,    g_gz);
    cudaGetSymbolAddress((void**)&p_heads, g_heads);
    cudaGetSymbolAddress((void**)&p_hbuf,  g_h);
    cudaGetSymbolAddress((void**)&p_wcat,  g_Wcat);
    cudaGetSymbolAddress((void**)&p_wz,    g_Wz);
    cudaGetSymbolAddress((void**)&p_whead, g_Whead);
    cudaGetSymbolAddress((void**)&p_w2r,   g_w2r);
    cudaGetSymbolAddress((void**)&p_w3r,   g_w3r);
    cudaGetSymbolAddress((void**)&p_biasI, g_biasI);

    k_setup<<<(BB*MEMN*KSZ + 255)/256, 256>>>(mem0, lwi, lwh, lb, wk, wwk, wv,
                                              c2w, c3w, out, out_size);

    // encoder
    k_convf<<<NFRM, 256, CONVF_SMEM_FLOATS * 4>>>(x, c1w, c1b, p_w2r, c2b, p_w3r, c3b);
    // fc1 (chunked, K=512)
    k_tc<<<dim3(2, 80), 256>>>(p_h3, 512, fc1w, 512, fc1b, p_fc1, 256, 512, 2);
    // fc2: split-K x2 partials; combine in ctxnorm
    k_tcs<<<dim3(1, 80, 2), 256, TCS_SMEM_BYTES>>>(p_fc1, 256, fc2w, 256, nullptr,
                                                   p_fc2p, 128, NFRM*DD, 0);
    k_ctxnorm<<<BB, 128>>>(fc2b, gamma, beta);
    // Gz = z @ Wz^T + biasI (interleaved cols)
    k_tcs<<<dim3(8, 80, 1), 256, TCS_SMEM_BYTES>>>(p_z, 128, p_wz, 128, p_biasI,
                                                   p_gz, 1024, 0, 1);

    for (int t = 0; t < TT; t++) {
        const float* hnxt = p_hbuf + ((t + 1) & 1)*BB*HH;
        // gates: [r|h] @ Wcat^T, full K=512, fused LSTM epilogue (64 blocks)
        k_g64<<<dim3(16, 4), 256>>>(nullptr, 0, p_wcat, 512, nullptr, 0, 512, 1, 1, t);
        // heads: h @ Whead^T, full K=256, tanh fused (48 blocks)
        k_g64<<<dim3(12, 4), 256>>>(hnxt, 256, p_whead, 256, p_heads, 768, 256, 0, 0, t);
        k_mem<<<BB, 256>>>(t, wo, wob, hnxt, out, out_size);
    }
}

// round 11
// speedup vs baseline: 1.2931x; 1.2931x over previous
#include <cuda_runtime.h>
#include <math.h>

#define BB 256
#define TT 20
#define DD 128
#define HH 256
#define KSZ 256
#define MEMN 20
#define YY 4
#define EPSF 1e-8f
#define NFRM (BB*TT)

// ---------------- device scratch ----------------
__device__ float g_h3[NFRM*512];
__device__ float g_fc1[NFRM*256];
__device__ float g_fc2p[2*NFRM*DD];     // fc2 split-K partials
__device__ float g_z[NFRM*DD];
__device__ float g_gz[NFRM*1024];       // precomputed z@Wz^T + lstm_b
__device__ float g_gates4[4*BB*1024];   // gates split-K partials
__device__ float g_hpart[2*BB*768];     // heads split-K partials
__device__ float g_hst[BB*HH];
__device__ float g_cst[BB*HH];
__device__ float g_r[BB*KSZ];
__device__ float g_M[BB*MEMN*KSZ];
__device__ float g_Wcat[1024*512];      // [Wr | Wh]
__device__ float g_Wz[1024*128];
__device__ float g_Whead[768*256];
__device__ float g_w2rh[16384];         // conv2 weights, fragment order, tf32-hi
__device__ float g_w2rl[16384];         // conv2 weights, residual lo
__device__ float g_w3rh[16384];
__device__ float g_w3rl[16384];

__device__ __forceinline__ float sigmf(float x){ return 1.f/(1.f+expf(-x)); }

// ---------------- tf32 mma helpers ----------------
__device__ __forceinline__ void mma8(float* c, const unsigned* a, const unsigned* b)
{
    asm volatile(
        "mma.sync.aligned.m16n8k8.row.col.f32.tf32.tf32.f32 "
        "{%0,%1,%2,%3},{%4,%5,%6,%7},{%8,%9},{%0,%1,%2,%3};"
        : "+f"(c[0]), "+f"(c[1]), "+f"(c[2]), "+f"(c[3])
        : "r"(a[0]), "r"(a[1]), "r"(a[2]), "r"(a[3]), "r"(b[0]), "r"(b[1]));
}
__device__ __forceinline__ void split2(float x, unsigned& hi, unsigned& lo)
{
    unsigned h = __float_as_uint(x) & 0xffffe000u;   // exact tf32 (truncated)
    hi = h;
    lo = __float_as_uint(x - __uint_as_float(h));
}
__device__ __forceinline__ void cpasync16(unsigned dst, const void* src)
{
    asm volatile("cp.async.cg.shared.global [%0], [%1], 16;\n" :: "r"(dst), "l"(src));
}

// ---------------- fused conv encoder (tensor-core conv2/conv3) ----------------
#define S_H1 1156
#define S_H2 13144
#define S_C3 16844
#define CONVF_SMEM_FLOATS 17900

__global__ void __launch_bounds__(256, 2) k_convf(
    const float* __restrict__ x,
    const float* __restrict__ w1, const float* __restrict__ b1,
    const float* __restrict__ w2rh, const float* __restrict__ w2rl,
    const float* __restrict__ b2,
    const float* __restrict__ w3rh, const float* __restrict__ w3rl,
    const float* __restrict__ b3)
{
    extern __shared__ float sm[];
    float* s_in = sm;
    float* s_h1 = sm + S_H1;
    float* s_h2 = sm + S_H2;
    float* s_c3 = sm + S_C3;
    const int f = blockIdx.x, tid = threadIdx.x;
    const int lane = tid & 31, warpid = tid >> 5;
    const int g = lane >> 2, tig = lane & 3;

    for (int i = tid; i < S_C3; i += 256) sm[i] = 0.f;
    __syncthreads();
    for (int i = tid; i < 1024; i += 256) {
        int iy = i >> 5, ix = i & 31;
        s_in[(iy+1)*34 + ix + 1] = x[f*1024 + i];
    }
    __syncthreads();

    // ---- conv1 (FFMA): 1->32ch, 32x32 -> 16x16, write channel-last ----
    for (int p = tid; p < 512; p += 256) {
        int oc = p >> 4, oy = p & 15;
        float bias = __ldg(b1 + oc);
        float acc[16];
        #pragma unroll
        for (int ox = 0; ox < 16; ox++) acc[ox] = bias;
        #pragma unroll
        for (int kh = 0; kh < 4; kh++) {
            const float* row = s_in + (2*oy+kh)*34;
            const float4 w = __ldg((const float4*)(w1 + oc*16 + kh*4));
            #pragma unroll
            for (int ox = 0; ox < 16; ox++) {
                acc[ox] += row[2*ox]*w.x + row[2*ox+1]*w.y
                         + row[2*ox+2]*w.z + row[2*ox+3]*w.w;
            }
        }
        int cellbase = (oy+1)*18 + 1;
        #pragma unroll
        for (int ox = 0; ox < 16; ox++)
            s_h1[(cellbase + ox)*37 + oc] = fmaxf(acc[ox], 0.f);
    }
    __syncthreads();

    // ---- conv2 (tf32 mma): weights pre-split hi/lo ----
    {
        const int wm = warpid & 3, wn = warpid >> 2;
        float acc[2][4] = {{0.f,0.f,0.f,0.f},{0.f,0.f,0.f,0.f}};
        int pA = wm*16 + g, pB = pA + 8;
        int oyA = pA >> 3, oxA = pA & 7;
        int oyB = pB >> 3, oxB = pB & 7;
        #pragma unroll 1
        for (int khw = 0; khw < 16; khw++) {
            int kh = khw >> 2, kw = khw & 3;
            const float* hA = s_h1 + ((2*oyA + kh)*18 + 2*oxA + kw)*37;
            const float* hB = s_h1 + ((2*oyB + kh)*18 + 2*oxB + kw)*37;
            #pragma unroll
            for (int ick = 0; ick < 4; ick++) {
                int ic0 = ick*8;
                unsigned ahi[4], alo[4];
                split2(hA[ic0+tig],   ahi[0], alo[0]);
                split2(hB[ic0+tig],   ahi[1], alo[1]);
                split2(hA[ic0+tig+4], ahi[2], alo[2]);
                split2(hB[ic0+tig+4], ahi[3], alo[3]);
                int idx128 = (khw*4 + ick)*2;
                #pragma unroll
                for (int ni = 0; ni < 2; ni++) {
                    int n8i = wn*2 + ni;
                    unsigned bhi[2], blo[2];
                    int o0 = ((idx128+0)*4 + n8i)*32 + lane;
                    int o1 = ((idx128+1)*4 + n8i)*32 + lane;
                    bhi[0] = __float_as_uint(__ldg(w2rh + o0));
                    bhi[1] = __float_as_uint(__ldg(w2rh + o1));
                    blo[0] = __float_as_uint(__ldg(w2rl + o0));
                    blo[1] = __float_as_uint(__ldg(w2rl + o1));
                    mma8(acc[ni], ahi, bhi);
                    mma8(acc[ni], alo, bhi);
                    mma8(acc[ni], ahi, blo);
                }
            }
        }
        int cellA = (oyA+1)*10 + oxA + 1;
        int cellB = (oyB+1)*10 + oxB + 1;
        #pragma unroll
        for (int ni = 0; ni < 2; ni++) {
            int col0 = wn*16 + ni*8 + 2*tig;
            float bb0 = __ldg(b2 + col0), bb1 = __ldg(b2 + col0 + 1);
            s_h2[cellA*37 + col0]     = fmaxf(acc[ni][0] + bb0, 0.f);
            s_h2[cellA*37 + col0 + 1] = fmaxf(acc[ni][1] + bb1, 0.f);
            s_h2[cellB*37 + col0]     = fmaxf(acc[ni][2] + bb0, 0.f);
            s_h2[cellB*37 + col0 + 1] = fmaxf(acc[ni][3] + bb1, 0.f);
        }
    }
    __syncthreads();

    // ---- conv3 (tf32 mma, 2-way K-split across warps), pre-split weights ----
    {
        const int n8i = warpid & 3, khalf = warpid >> 2;
        float acc[4] = {0.f, 0.f, 0.f, 0.f};
        int pA = g, pB = g + 8;
        int oyA = pA >> 2, oxA = pA & 3;
        int oyB = pB >> 2, oxB = pB & 3;
        #pragma unroll 1
        for (int kk = 0; kk < 8; kk++) {
            int khw = khalf*8 + kk;
            int kh = khw >> 2, kw = khw & 3;
            const float* hA = s_h2 + ((2*oyA + kh)*10 + 2*oxA + kw)*37;
            const float* hB = s_h2 + ((2*oyB + kh)*10 + 2*oxB + kw)*37;
            #pragma unroll
            for (int ick = 0; ick < 4; ick++) {
                int ic0 = ick*8;
                unsigned ahi[4], alo[4];
                split2(hA[ic0+tig],   ahi[0], alo[0]);
                split2(hB[ic0+tig],   ahi[1], alo[1]);
                split2(hA[ic0+tig+4], ahi[2], alo[2]);
                split2(hB[ic0+tig+4], ahi[3], alo[3]);
                int idx128 = (khw*4 + ick)*2;
                unsigned bhi[2], blo[2];
                int o0 = ((idx128+0)*4 + n8i)*32 + lane;
                int o1 = ((idx128+1)*4 + n8i)*32 + lane;
                bhi[0] = __float_as_uint(__ldg(w3rh + o0));
                bhi[1] = __float_as_uint(__ldg(w3rh + o1));
                blo[0] = __float_as_uint(__ldg(w3rl + o0));
                blo[1] = __float_as_uint(__ldg(w3rl + o1));
                mma8(acc, ahi, bhi);
                mma8(acc, alo, bhi);
                mma8(acc, ahi, blo);
            }
        }
        int col0 = n8i*8 + 2*tig;
        s_c3[(khalf*16 + g)*33 + col0]       = acc[0];
        s_c3[(khalf*16 + g)*33 + col0 + 1]   = acc[1];
        s_c3[(khalf*16 + g+8)*33 + col0]     = acc[2];
        s_c3[(khalf*16 + g+8)*33 + col0 + 1] = acc[3];
    }
    __syncthreads();
    for (int idx = tid; idx < 512; idx += 256) {
        int p = idx >> 5, oc = idx & 31;
        float v = s_c3[p*33 + oc] + s_c3[(16+p)*33 + oc] + __ldg(b3 + oc);
        g_h3[f*512 + oc*16 + p] = fmaxf(v, 0.f);
    }
}

// ---------------- chunked 3xTF32 GEMM (fc1, K=512) ----------------
__global__ void __launch_bounds__(256) k_tc(
    const float* __restrict__ A, int lda,
    const float* __restrict__ W, int ldw,
    const float* __restrict__ bias,
    float* __restrict__ C, int ldc, int K, int ep)
{
    __shared__ float sA[32][72];
    __shared__ float sW[32][136];

    const int tid = threadIdx.x;
    const int warpid = tid >> 5, lane = tid & 31;
    const int g = lane >> 2, tig = lane & 3;
    const int wm = warpid >> 2, wn = warpid & 3;
    const int mtile = blockIdx.y, ntile = blockIdx.x;

    const int arow0 = tid & 63, akq0 = tid >> 6;
    const int akq1 = akq0 + 4;
    const float* Abase0 = A + (mtile*64 + arow0)*lda + akq0*4;
    const float* Abase1 = A + (mtile*64 + arow0)*lda + akq1*4;

    float acc[2][4][4];
    #pragma unroll
    for (int mi = 0; mi < 2; mi++)
        #pragma unroll
        for (int ni = 0; ni < 4; ni++)
            #pragma unroll
            for (int q = 0; q < 4; q++) acc[mi][ni][q] = 0.f;

    const int nkc = K >> 5;
    float4 pa0 = *(const float4*)(Abase0);
    float4 pa1 = *(const float4*)(Abase1);
    float4 pw[4];
    #pragma unroll
    for (int q = 0; q < 4; q++) {
        int idx = tid + q*256;
        int n = idx & 127, kq = idx >> 7;
        pw[q] = *(const float4*)(W + (ntile*128 + n)*ldw + kq*4);
    }

    for (int kt = 0; kt < nkc; kt++) {
        sA[akq0*4+0][arow0] = pa0.x; sA[akq0*4+1][arow0] = pa0.y;
        sA[akq0*4+2][arow0] = pa0.z; sA[akq0*4+3][arow0] = pa0.w;
        sA[akq1*4+0][arow0] = pa1.x; sA[akq1*4+1][arow0] = pa1.y;
        sA[akq1*4+2][arow0] = pa1.z; sA[akq1*4+3][arow0] = pa1.w;
        #pragma unroll
        for (int q = 0; q < 4; q++) {
            int idx = tid + q*256;
            int n = idx & 127, kq = idx >> 7;
            sW[kq*4+0][n] = pw[q].x; sW[kq*4+1][n] = pw[q].y;
            sW[kq*4+2][n] = pw[q].z; sW[kq*4+3][n] = pw[q].w;
        }
        __syncthreads();

        if (kt + 1 < nkc) {
            int kb = (kt+1) << 5;
            pa0 = *(const float4*)(Abase0 + kb);
            pa1 = *(const float4*)(Abase1 + kb);
            #pragma unroll
            for (int q = 0; q < 4; q++) {
                int idx = tid + q*256;
                int n = idx & 127, kq = idx >> 7;
                pw[q] = *(const float4*)(W + (ntile*128 + n)*ldw + kb + kq*4);
            }
        }

        #pragma unroll
        for (int kk = 0; kk < 4; kk++) {
            const int k0 = kk*8 + tig, k1 = k0 + 4;
            unsigned ahi[2][4], alo[2][4], bhi[4][2], blo[4][2];
            #pragma unroll
            for (int mi = 0; mi < 2; mi++) {
                int r0 = wm*32 + mi*16 + g;
                split2(sA[k0][r0],    ahi[mi][0], alo[mi][0]);
                split2(sA[k0][r0+8],  ahi[mi][1], alo[mi][1]);
                split2(sA[k1][r0],    ahi[mi][2], alo[mi][2]);
                split2(sA[k1][r0+8],  ahi[mi][3], alo[mi][3]);
            }
            #pragma unroll
            for (int ni = 0; ni < 4; ni++) {
                int c0 = wn*32 + ni*8 + g;
                split2(sW[k0][c0], bhi[ni][0], blo[ni][0]);
                split2(sW[k1][c0], bhi[ni][1], blo[ni][1]);
            }
            #pragma unroll
            for (int mi = 0; mi < 2; mi++)
                #pragma unroll
                for (int ni = 0; ni < 4; ni++) {
                    mma8(acc[mi][ni], ahi[mi], bhi[ni]);
                    mma8(acc[mi][ni], alo[mi], bhi[ni]);
                    mma8(acc[mi][ni], ahi[mi], blo[ni]);
                }
        }
        __syncthreads();
    }

    #pragma unroll
    for (int mi = 0; mi < 2; mi++) {
        #pragma unroll
        for (int ni = 0; ni < 4; ni++) {
            int row0 = mtile*64 + wm*32 + mi*16 + g;
            int col0 = ntile*128 + wn*32 + ni*8 + 2*tig;
            float v0 = acc[mi][ni][0], v1 = acc[mi][ni][1];
            float v2 = acc[mi][ni][2], v3 = acc[mi][ni][3];
            if (ep >= 1) {
                float b0 = bias[col0], b1 = bias[col0+1];
                v0 += b0; v1 += b1; v2 += b0; v3 += b1;
            }
            if (ep == 2) {
                v0 = fmaxf(v0, 0.f); v1 = fmaxf(v1, 0.f);
                v2 = fmaxf(v2, 0.f); v3 = fmaxf(v3, 0.f);
            }
            float* p = C + row0*ldc + col0;
            p[0] = v0; p[1] = v1;
            p[8*ldc] = v2; p[8*ldc + 1] = v3;
        }
    }
}

// ---------------- single-stage 3xTF32 GEMM (K=128 per block, cp.async) -------------
#define TCS_SMEM_BYTES ((64*132 + 128*132)*4)

__global__ void __launch_bounds__(256) k_tcs(
    const float* __restrict__ A, int lda,
    const float* __restrict__ W, int ldw,
    const float* __restrict__ bias,
    float* __restrict__ C, int ldc,
    int partStride, int mode, int ep)
{
    extern __shared__ float smem[];
    float* sA = smem;
    float* sW = smem + 64*132;
    const int tid = threadIdx.x;
    const int warpid = tid >> 5, lane = tid & 31;
    const int g = lane >> 2, tig = lane & 3;
    const int wm = warpid >> 2, wn = warpid & 3;
    const int mtile = blockIdx.y, ntile = blockIdx.x, z = blockIdx.z;
    const int kStart = z*128;

    const float* Ab; int abase, ldae;
    if (mode == 1) {
        if (kStart < KSZ) { Ab = g_r;   abase = kStart; }
        else              { Ab = g_hst; abase = kStart - KSZ; }
        ldae = 256;
    } else { Ab = A; abase = kStart; ldae = lda; }
    float* Cp = C + z*partStride;

    #pragma unroll
    for (int q = 0; q < 8; q++) {
        int c = tid + q*256;
        int row = c >> 5, kc = c & 31;
        const float* src = Ab + (mtile*64 + row)*ldae + abase + kc*4;
        cpasync16((unsigned)__cvta_generic_to_shared(sA + row*132 + kc*4), src);
    }
    #pragma unroll
    for (int q = 0; q < 16; q++) {
        int c = tid + q*256;
        int col = c >> 5, kc = c & 31;
        const float* src = W + (ntile*128 + col)*ldw + kStart + kc*4;
        cpasync16((unsigned)__cvta_generic_to_shared(sW + col*132 + kc*4), src);
    }
    asm volatile("cp.async.commit_group;\n");
    asm volatile("cp.async.wait_group 0;\n");
    __syncthreads();

    float acc[2][4][4];
    #pragma unroll
    for (int mi = 0; mi < 2; mi++)
        #pragma unroll
        for (int ni = 0; ni < 4; ni++)
            #pragma unroll
            for (int q = 0; q < 4; q++) acc[mi][ni][q] = 0.f;

    #pragma unroll 2
    for (int kk = 0; kk < 16; kk++) {
        const int k0 = kk*8 + tig, k1 = k0 + 4;
        unsigned ahi[2][4], alo[2][4], bhi[4][2], blo[4][2];
        #pragma unroll
        for (int mi = 0; mi < 2; mi++) {
            const float* r0 = sA + (wm*32 + mi*16 + g)*132;
            const float* r1 = r0 + 8*132;
            split2(r0[k0], ahi[mi][0], alo[mi][0]);
            split2(r1[k0], ahi[mi][1], alo[mi][1]);
            split2(r0[k1], ahi[mi][2], alo[mi][2]);
            split2(r1[k1], ahi[mi][3], alo[mi][3]);
        }
        #pragma unroll
        for (int ni = 0; ni < 4; ni++) {
            const float* c0 = sW + (wn*32 + ni*8 + g)*132;
            split2(c0[k0], bhi[ni][0], blo[ni][0]);
            split2(c0[k1], bhi[ni][1], blo[ni][1]);
        }
        #pragma unroll
        for (int mi = 0; mi < 2; mi++)
            #pragma unroll
            for (int ni = 0; ni < 4; ni++) {
                mma8(acc[mi][ni], ahi[mi], bhi[ni]);
                mma8(acc[mi][ni], alo[mi], bhi[ni]);
                mma8(acc[mi][ni], ahi[mi], blo[ni]);
            }
    }

    #pragma unroll
    for (int mi = 0; mi < 2; mi++) {
        #pragma unroll
        for (int ni = 0; ni < 4; ni++) {
            int row0 = mtile*64 + wm*32 + mi*16 + g;
            int col0 = ntile*128 + wn*32 + ni*8 + 2*tig;
            float v0 = acc[mi][ni][0], v1 = acc[mi][ni][1];
            float v2 = acc[mi][ni][2], v3 = acc[mi][ni][3];
            if (ep >= 1) {
                float b0 = bias[col0], b1 = bias[col0+1];
                v0 += b0; v1 += b1; v2 += b0; v3 += b1;
            }
            float* p = Cp + row0*ldc + col0;
            p[0] = v0; p[1] = v1;
            p[8*ldc] = v2; p[8*ldc + 1] = v3;
        }
    }
}

// ---------------- context norm over time, fused fc2 combine + bias + relu ------------
__global__ void k_ctxnorm(const float* __restrict__ fc2b,
                          const float* __restrict__ gamma, const float* __restrict__ beta)
{
    int b = blockIdx.x, d = threadIdx.x;
    float bias = fc2b[d];
    float v[TT];
    float s = 0.f, s2 = 0.f;
    #pragma unroll
    for (int t = 0; t < TT; t++) {
        int idx = (b*TT+t)*DD + d;
        v[t] = fmaxf(g_fc2p[idx] + g_fc2p[NFRM*DD + idx] + bias, 0.f);
        s += v[t]; s2 += v[t]*v[t];
    }
    float mu  = s / TT;
    float var = (s2 - TT*mu*mu) / (TT - 1);
    float inv = 1.f / sqrtf(var + EPSF);
    float ga = gamma[d], be = beta[d];
    #pragma unroll
    for (int t = 0; t < TT; t++)
        g_z[(b*TT+t)*DD + d] = (v[t] - mu)*inv*ga + be;
}

// ---------------- setup (conv weights restaged + pre-split hi/lo) -------------------
__global__ void k_setup(const float* __restrict__ mem0,
                        const float* __restrict__ wi, const float* __restrict__ wh,
                        const float* __restrict__ wk, const float* __restrict__ wwk,
                        const float* __restrict__ wv,
                        const float* __restrict__ w2, const float* __restrict__ w3,
                        float* __restrict__ out, int out_size)
{
    int i = blockIdx.x*256 + threadIdx.x;
    if (i < BB*MEMN*KSZ) g_M[i] = mem0[i % (MEMN*KSZ)];
    if (i < 1024*512) {
        int j = i >> 9, c = i & 511;
        g_Wcat[i] = (c < 256) ? wi[j*384 + 128 + c] : wh[j*256 + (c-256)];
    }
    if (i < 1024*128) {
        int j = i >> 7, c = i & 127;
        g_Wz[i] = wi[j*384 + c];
    }
    if (i < 768*256) {
        int n = i >> 8;
        g_Whead[i] = (n < 256) ? wk[i] : ((n < 512) ? wwk[i - 256*256] : wv[i - 512*256]);
    }
    if (i < 16384) {
        int lane = i & 31;
        int j = i >> 5;
        int n8i = j & 3; j >>= 2;
        int half = j & 1; j >>= 1;
        int ick = j & 3;
        int khw = j >> 2;
        int n = n8i*8 + (lane >> 2);
        int kic = ick*8 + (lane & 3) + half*4;
        float v2 = w2[n*512 + kic*16 + khw];
        float v3 = w3[n*512 + kic*16 + khw];
        unsigned h2 = __float_as_uint(v2) & 0xffffe000u;
        unsigned h3 = __float_as_uint(v3) & 0xffffe000u;
        g_w2rh[i] = __uint_as_float(h2);
        g_w2rl[i] = v2 - __uint_as_float(h2);
        g_w3rh[i] = __uint_as_float(h3);
        g_w3rl[i] = v3 - __uint_as_float(h3);
    }
    if (i < BB*HH) { g_hst[i] = 0.f; g_cst[i] = 0.f; }
    if (i < BB*KSZ) g_r[i] = 0.f;
    if (i < out_size) out[i] = 0.f;
}

// ---------------- per-step: LSTM update (sums gz + 4 gate partials, float4) ----------
__global__ void k_lstm(int t)
{
    int idx = blockIdx.x*256 + threadIdx.x;
    int b = idx >> 6, j = (idx & 63) << 2;
    const float* gz = g_gz + (b*TT + t)*1024;
    float4 g[4];
    #pragma unroll
    for (int gt = 0; gt < 4; gt++) g[gt] = *(const float4*)(gz + gt*256 + j);
    #pragma unroll
    for (int z = 0; z < 4; z++) {
        const float* gp = g_gates4 + z*(BB*1024) + b*1024;
        #pragma unroll
        for (int gt = 0; gt < 4; gt++) {
            float4 p = *(const float4*)(gp + gt*256 + j);
            g[gt].x += p.x; g[gt].y += p.y; g[gt].z += p.z; g[gt].w += p.w;
        }
    }
    float4 c = *(const float4*)(g_cst + b*HH + j);
    float4 cn, hn;
    cn.x = sigmf(g[1].x)*c.x + sigmf(g[0].x)*tanhf(g[2].x);
    cn.y = sigmf(g[1].y)*c.y + sigmf(g[0].y)*tanhf(g[2].y);
    cn.z = sigmf(g[1].z)*c.z + sigmf(g[0].z)*tanhf(g[2].z);
    cn.w = sigmf(g[1].w)*c.w + sigmf(g[0].w)*tanhf(g[2].w);
    hn.x = sigmf(g[3].x)*tanhf(cn.x);
    hn.y = sigmf(g[3].y)*tanhf(cn.y);
    hn.z = sigmf(g[3].z)*tanhf(cn.z);
    hn.w = sigmf(g[3].w)*tanhf(cn.w);
    *(float4*)(g_cst + b*HH + j) = cn;
    *(float4*)(g_hst + b*HH + j) = hn;
}

// ---------------- per-step: memory read/write + (last step) output ----------------
__global__ void __launch_bounds__(256) k_mem(int t, const float* __restrict__ wo,
                                             const float* __restrict__ wob,
                                             float* __restrict__ out, int out_size)
{
    __shared__ float s_kr[256], s_kw[256], s_rnew[256];
    __shared__ float s_simr[MEMN], s_simw[MEMN];
    __shared__ float s_wr[4], s_ws[4];
    __shared__ int   s_ir[4], s_iw[4];
    __shared__ float s_red[16];
    __shared__ float s_nrm[2];
    __shared__ float s_y[4];

    int b = blockIdx.x, tid = threadIdx.x;
    int lane = tid & 31, wid = tid >> 5;

    float kr = 0.f, kw = 0.f, vvs = 0.f;
    #pragma unroll
    for (int z = 0; z < 2; z++) {
        const float* hp = g_hpart + z*(BB*768) + b*768;
        kr  += hp[tid];
        kw  += hp[256 + tid];
        vvs += hp[512 + tid];
    }
    float vv = tanhf(vvs);
    s_kr[tid] = kr;
    s_kw[tid] = kw;

    float pr = kr*kr, pw = kw*kw;
    #pragma unroll
    for (int o = 16; o > 0; o >>= 1) {
        pr += __shfl_xor_sync(0xffffffffu, pr, o);
        pw += __shfl_xor_sync(0xffffffffu, pw, o);
    }
    if (lane == 0) { s_red[wid] = pr; s_red[8 + wid] = pw; }
    __syncthreads();
    if (tid == 0) {
        float sr = 0.f, sw = 0.f;
        #pragma unroll
        for (int w = 0; w < 8; w++) { sr += s_red[w]; sw += s_red[8 + w]; }
        s_nrm[0] = 1.f / (sqrtf(sr) + EPSF);
        s_nrm[1] = 1.f / (sqrtf(sw) + EPSF);
    }
    __syncthreads();

    for (int n = wid; n < MEMN; n += 8) {
        const float* Mr = g_M + (b*MEMN + n)*KSZ;
        float dr = 0.f, dw = 0.f, nn = 0.f;
        #pragma unroll
        for (int d0 = 0; d0 < KSZ; d0 += 32) {
            float m = Mr[d0 + lane];
            dr += s_kr[d0 + lane]*m;
            dw += s_kw[d0 + lane]*m;
            nn += m*m;
        }
        #pragma unroll
        for (int o = 16; o > 0; o >>= 1) {
            dr += __shfl_xor_sync(0xffffffffu, dr, o);
            dw += __shfl_xor_sync(0xffffffffu, dw, o);
            nn += __shfl_xor_sync(0xffffffffu, nn, o);
        }
        if (lane == 0) {
            float mi = 1.f / (sqrtf(nn) + EPSF);
            s_simr[n] = dr * s_nrm[0] * mi;
            s_simw[n] = dw * s_nrm[1] * mi;
        }
    }
    __syncthreads();

    if (tid < 2) {
        const float* sims = tid ? s_simw : s_simr;
        float* wout = tid ? s_ws : s_wr;
        int*   iout = tid ? s_iw : s_ir;
        unsigned used = 0;
        float vals[4];
        #pragma unroll
        for (int k = 0; k < 4; k++) {
            float best = -1e30f; int bi = 0;
            for (int n = 0; n < MEMN; n++) {
                if (!((used >> n) & 1u) && sims[n] > best) { best = sims[n]; bi = n; }
            }
            used |= 1u << bi;
            iout[k] = bi; vals[k] = best;
        }
        float mx = vals[0], ssum = 0.f, e[4];
        #pragma unroll
        for (int k = 0; k < 4; k++) { e[k] = expf(vals[k] - mx); ssum += e[k]; }
        #pragma unroll
        for (int k = 0; k < 4; k++) wout[k] = e[k] / ssum;
    }
    __syncthreads();

    float r = 0.f;
    #pragma unroll
    for (int k = 0; k < 4; k++)
        r += s_wr[k] * g_M[(b*MEMN + s_ir[k])*KSZ + tid];
    g_r[b*KSZ + tid] = r;
    s_rnew[tid] = r;

    #pragma unroll
    for (int k = 0; k < 4; k++)
        g_M[(b*MEMN + s_iw[k])*KSZ + tid] += s_ws[k] * vv;

    if (t == TT - 1) {
        __syncthreads();
        if (wid < 4) {
            const float* wrow = wo + wid*512;
            float p = 0.f;
            for (int j = lane; j < 256; j += 32) p += wrow[j]       * g_hst[b*HH + j];
            for (int j = lane; j < 256; j += 32) p += wrow[256 + j] * s_rnew[j];
            #pragma unroll
            for (int o = 16; o > 0; o >>= 1) p += __shfl_xor_sync(0xffffffffu, p, o);
            if (lane == 0) s_y[wid] = p + wob[wid];
        }
        __syncthreads();
        if (tid < 4 && (b*4 + tid) < out_size) out[b*4 + tid] = s_y[tid];
        if (tid == 0 && out_size >= BB*YY + BB) {
            int am = 0; float bv = s_y[0];
            #pragma unroll
            for (int o = 1; o < 4; o++) if (s_y[o] > bv) { bv = s_y[o]; am = o; }
            out[BB*YY + b] = (float)am;
        }
    }
}

// ---------------- launch ----------------
extern "C" void kernel_launch(void* const* d_in, const int* in_sizes, int n_in,
                              void* d_out, int out_size)
{
    const float* x    = (const float*)d_in[0];
    const float* c1w  = (const float*)d_in[1];
    const float* c1b  = (const float*)d_in[2];
    const float* c2w  = (const float*)d_in[3];
    const float* c2b  = (const float*)d_in[4];
    const float* c3w  = (const float*)d_in[5];
    const float* c3b  = (const float*)d_in[6];
    const float* fc1w = (const float*)d_in[7];
    const float* fc1b = (const float*)d_in[8];
    const float* fc2w = (const float*)d_in[9];
    const float* fc2b = (const float*)d_in[10];
    const float* gamma= (const float*)d_in[11];
    const float* beta = (const float*)d_in[12];
    const float* lwi  = (const float*)d_in[13];
    const float* lwh  = (const float*)d_in[14];
    const float* lb   = (const float*)d_in[15];
    const float* wk   = (const float*)d_in[16];
    const float* wwk  = (const float*)d_in[17];
    const float* wv   = (const float*)d_in[18];
    const float* wo   = (const float*)d_in[19];
    const float* wob  = (const float*)d_in[20];
    const float* mem0 = (const float*)d_in[21];
    float* out = (float*)d_out;

    cudaFuncSetAttribute(k_convf, cudaFuncAttributeMaxDynamicSharedMemorySize,
                         CONVF_SMEM_FLOATS * 4);
    cudaFuncSetAttribute(k_tcs, cudaFuncAttributeMaxDynamicSharedMemorySize,
                         TCS_SMEM_BYTES);

    float *p_h3, *p_fc1, *p_fc2p, *p_z, *p_gz, *p_g4, *p_hp, *p_h;
    float *p_wcat, *p_wz, *p_whead;
    float *p_w2rh, *p_w2rl, *p_w3rh, *p_w3rl;
    cudaGetSymbolAddress((void**)&p_h3,    g_h3);
    cudaGetSymbolAddress((void**)&p_fc1,   g_fc1);
    cudaGetSymbolAddress((void**)&p_fc2p,  g_fc2p);
    cudaGetSymbolAddress((void**)&p_z,     g_z);
    cudaGetSymbolAddress((void**)&p_gz,    g_gz);
    cudaGetSymbolAddress((void**)&p_g4,    g_gates4);
    cudaGetSymbolAddress((void**)&p_hp,    g_hpart);
    cudaGetSymbolAddress((void**)&p_h,     g_hst);
    cudaGetSymbolAddress((void**)&p_wcat,  g_Wcat);
    cudaGetSymbolAddress((void**)&p_wz,    g_Wz);
    cudaGetSymbolAddress((void**)&p_whead, g_Whead);
    cudaGetSymbolAddress((void**)&p_w2rh,  g_w2rh);
    cudaGetSymbolAddress((void**)&p_w2rl,  g_w2rl);
    cudaGetSymbolAddress((void**)&p_w3rh,  g_w3rh);
    cudaGetSymbolAddress((void**)&p_w3rl,  g_w3rl);

    k_setup<<<(BB*MEMN*KSZ + 255)/256, 256>>>(mem0, lwi, lwh, wk, wwk, wv,
                                              c2w, c3w, out, out_size);

    // encoder (tensor-core conv, pre-split weights)
    k_convf<<<NFRM, 256, CONVF_SMEM_FLOATS * 4>>>(x, c1w, c1b,
                                                  p_w2rh, p_w2rl, c2b,
                                                  p_w3rh, p_w3rl, c3b);
    // fc1 (chunked, K=512)
    k_tc<<<dim3(2, 80), 256>>>(p_h3, 512, fc1w, 512, fc1b, p_fc1, 256, 512, 2);
    // fc2: split-K x2 partials; combine in ctxnorm
    k_tcs<<<dim3(1, 80, 2), 256, TCS_SMEM_BYTES>>>(p_fc1, 256, fc2w, 256, nullptr,
                                                   p_fc2p, 128, NFRM*DD, 0, 0);
    k_ctxnorm<<<BB, 128>>>(fc2b, gamma, beta);
    // Gz = z @ Wz^T + lstm_b (single-stage, K=128)
    k_tcs<<<dim3(8, 80, 1), 256, TCS_SMEM_BYTES>>>(p_z, 128, p_wz, 128, lb,
                                                   p_gz, 1024, 0, 0, 1);

    for (int t = 0; t < TT; t++) {
        // gates: [r|h] @ Wcat^T, split-K x4, single-stage
        k_tcs<<<dim3(8, 4, 4), 256, TCS_SMEM_BYTES>>>(nullptr, 0, p_wcat, 512, nullptr,
                                                      p_g4, 1024, BB*1024, 1, 0);
        k_lstm<<<64, 256>>>(t);
        // heads: h @ Whead^T, split-K x2, single-stage
        k_tcs<<<dim3(6, 4, 2), 256, TCS_SMEM_BYTES>>>(p_h, 256, p_whead, 256, nullptr,
                                                      p_hp, 768, BB*768, 0, 0);
        k_mem<<<BB, 256>>>(t, wo, wob, out, out_size);
    }
}

// round 14
// speedup vs baseline: 1.3463x; 1.0411x over previous
#include <cuda_runtime.h>
#include <math.h>

#define BB 256
#define TT 20
#define DD 128
#define HH 256
#define KSZ 256
#define MEMN 20
#define YY 4
#define EPSF 1e-8f
#define NFRM (BB*TT)

// ---------------- device scratch ----------------
__device__ float g_h3[NFRM*512];
__device__ float g_fc1[NFRM*256];
__device__ float g_fc2p[2*NFRM*DD];     // fc2 split-K partials
__device__ float g_z[NFRM*DD];
__device__ float g_gz[NFRM*1024];       // precomputed z@Wz^T + lstm_b
__device__ float g_gates4[4*BB*1024];   // gates split-K partials
__device__ float g_hpart[2*BB*768];     // heads split-K partials
__device__ float g_hst[BB*HH];
__device__ float g_cst[BB*HH];
__device__ float g_r[BB*KSZ];
__device__ float g_M[BB*MEMN*KSZ];
__device__ float g_Wcat[1024*512];      // [Wr | Wh]
__device__ float g_Wz[1024*128];
__device__ float g_Whead[768*256];
__device__ float g_w2r[16384];          // conv2 weights, mma-fragment order
__device__ float g_w3r[16384];          // conv3 weights, mma-fragment order

__device__ __forceinline__ float sigmf(float x){ return 1.f/(1.f+expf(-x)); }

// ---------------- tf32 mma helpers ----------------
__device__ __forceinline__ void mma8(float* c, const unsigned* a, const unsigned* b)
{
    asm volatile(
        "mma.sync.aligned.m16n8k8.row.col.f32.tf32.tf32.f32 "
        "{%0,%1,%2,%3},{%4,%5,%6,%7},{%8,%9},{%0,%1,%2,%3};"
        : "+f"(c[0]), "+f"(c[1]), "+f"(c[2]), "+f"(c[3])
        : "r"(a[0]), "r"(a[1]), "r"(a[2]), "r"(a[3]), "r"(b[0]), "r"(b[1]));
}
__device__ __forceinline__ void split2(float x, unsigned& hi, unsigned& lo)
{
    unsigned h = __float_as_uint(x) & 0xffffe000u;   // exact tf32 (truncated)
    hi = h;
    lo = __float_as_uint(x - __uint_as_float(h));
}
__device__ __forceinline__ void cpasync16(unsigned dst, const void* src)
{
    asm volatile("cp.async.cg.shared.global [%0], [%1], 16;\n" :: "r"(dst), "l"(src));
}

// ---------------- fused conv encoder (tensor-core conv2/conv3) ----------------
#define S_H1 1156
#define S_H2 13144
#define S_C3 16844
#define CONVF_SMEM_FLOATS 17900

__global__ void __launch_bounds__(256, 2) k_convf(
    const float* __restrict__ x,
    const float* __restrict__ w1, const float* __restrict__ b1,
    const float* __restrict__ w2r, const float* __restrict__ b2,
    const float* __restrict__ w3r, const float* __restrict__ b3)
{
    extern __shared__ float sm[];
    float* s_in = sm;
    float* s_h1 = sm + S_H1;
    float* s_h2 = sm + S_H2;
    float* s_c3 = sm + S_C3;
    const int f = blockIdx.x, tid = threadIdx.x;
    const int lane = tid & 31, warpid = tid >> 5;
    const int g = lane >> 2, tig = lane & 3;

    for (int i = tid; i < S_C3; i += 256) sm[i] = 0.f;
    __syncthreads();
    for (int i = tid; i < 1024; i += 256) {
        int iy = i >> 5, ix = i & 31;
        s_in[(iy+1)*34 + ix + 1] = x[f*1024 + i];
    }
    __syncthreads();

    // ---- conv1 (FFMA): 1->32ch, 32x32 -> 16x16, write channel-last ----
    for (int p = tid; p < 512; p += 256) {
        int oc = p >> 4, oy = p & 15;
        float bias = __ldg(b1 + oc);
        float acc[16];
        #pragma unroll
        for (int ox = 0; ox < 16; ox++) acc[ox] = bias;
        #pragma unroll
        for (int kh = 0; kh < 4; kh++) {
            const float* row = s_in + (2*oy+kh)*34;
            const float4 w = __ldg((const float4*)(w1 + oc*16 + kh*4));
            #pragma unroll
            for (int ox = 0; ox < 16; ox++) {
                acc[ox] += row[2*ox]*w.x + row[2*ox+1]*w.y
                         + row[2*ox+2]*w.z + row[2*ox+3]*w.w;
            }
        }
        int cellbase = (oy+1)*18 + 1;
        #pragma unroll
        for (int ox = 0; ox < 16; ox++)
            s_h1[(cellbase + ox)*37 + oc] = fmaxf(acc[ox], 0.f);
    }
    __syncthreads();

    // ---- conv2 (tf32 mma) ----
    {
        const int wm = warpid & 3, wn = warpid >> 2;
        float acc[2][4] = {{0.f,0.f,0.f,0.f},{0.f,0.f,0.f,0.f}};
        int pA = wm*16 + g, pB = pA + 8;
        int oyA = pA >> 3, oxA = pA & 7;
        int oyB = pB >> 3, oxB = pB & 7;
        #pragma unroll 1
        for (int khw = 0; khw < 16; khw++) {
            int kh = khw >> 2, kw = khw & 3;
            const float* hA = s_h1 + ((2*oyA + kh)*18 + 2*oxA + kw)*37;
            const float* hB = s_h1 + ((2*oyB + kh)*18 + 2*oxB + kw)*37;
            #pragma unroll
            for (int ick = 0; ick < 4; ick++) {
                int ic0 = ick*8;
                unsigned ahi[4], alo[4];
                split2(hA[ic0+tig],   ahi[0], alo[0]);
                split2(hB[ic0+tig],   ahi[1], alo[1]);
                split2(hA[ic0+tig+4], ahi[2], alo[2]);
                split2(hB[ic0+tig+4], ahi[3], alo[3]);
                int idx128 = (khw*4 + ick)*2;
                #pragma unroll
                for (int ni = 0; ni < 2; ni++) {
                    int n8i = wn*2 + ni;
                    unsigned bhi[2], blo[2];
                    float b0 = __ldg(w2r + ((idx128+0)*4 + n8i)*32 + lane);
                    float b1v= __ldg(w2r + ((idx128+1)*4 + n8i)*32 + lane);
                    split2(b0,  bhi[0], blo[0]);
                    split2(b1v, bhi[1], blo[1]);
                    mma8(acc[ni], ahi, bhi);
                    mma8(acc[ni], alo, bhi);
                    mma8(acc[ni], ahi, blo);
                }
            }
        }
        int cellA = (oyA+1)*10 + oxA + 1;
        int cellB = (oyB+1)*10 + oxB + 1;
        #pragma unroll
        for (int ni = 0; ni < 2; ni++) {
            int col0 = wn*16 + ni*8 + 2*tig;
            float bb0 = __ldg(b2 + col0), bb1 = __ldg(b2 + col0 + 1);
            s_h2[cellA*37 + col0]     = fmaxf(acc[ni][0] + bb0, 0.f);
            s_h2[cellA*37 + col0 + 1] = fmaxf(acc[ni][1] + bb1, 0.f);
            s_h2[cellB*37 + col0]     = fmaxf(acc[ni][2] + bb0, 0.f);
            s_h2[cellB*37 + col0 + 1] = fmaxf(acc[ni][3] + bb1, 0.f);
        }
    }
    __syncthreads();

    // ---- conv3 (tf32 mma, 2-way K-split across warps) ----
    {
        const int n8i = warpid & 3, khalf = warpid >> 2;
        float acc[4] = {0.f, 0.f, 0.f, 0.f};
        int pA = g, pB = g + 8;
        int oyA = pA >> 2, oxA = pA & 3;
        int oyB = pB >> 2, oxB = pB & 3;
        #pragma unroll 1
        for (int kk = 0; kk < 8; kk++) {
            int khw = khalf*8 + kk;
            int kh = khw >> 2, kw = khw & 3;
            const float* hA = s_h2 + ((2*oyA + kh)*10 + 2*oxA + kw)*37;
            const float* hB = s_h2 + ((2*oyB + kh)*10 + 2*oxB + kw)*37;
            #pragma unroll
            for (int ick = 0; ick < 4; ick++) {
                int ic0 = ick*8;
                unsigned ahi[4], alo[4];
                split2(hA[ic0+tig],   ahi[0], alo[0]);
                split2(hB[ic0+tig],   ahi[1], alo[1]);
                split2(hA[ic0+tig+4], ahi[2], alo[2]);
                split2(hB[ic0+tig+4], ahi[3], alo[3]);
                int idx128 = (khw*4 + ick)*2;
                unsigned bhi[2], blo[2];
                float b0 = __ldg(w3r + ((idx128+0)*4 + n8i)*32 + lane);
                float b1v= __ldg(w3r + ((idx128+1)*4 + n8i)*32 + lane);
                split2(b0,  bhi[0], blo[0]);
                split2(b1v, bhi[1], blo[1]);
                mma8(acc, ahi, bhi);
                mma8(acc, alo, bhi);
                mma8(acc, ahi, blo);
            }
        }
        int col0 = n8i*8 + 2*tig;
        s_c3[(khalf*16 + g)*33 + col0]       = acc[0];
        s_c3[(khalf*16 + g)*33 + col0 + 1]   = acc[1];
        s_c3[(khalf*16 + g+8)*33 + col0]     = acc[2];
        s_c3[(khalf*16 + g+8)*33 + col0 + 1] = acc[3];
    }
    __syncthreads();
    for (int idx = tid; idx < 512; idx += 256) {
        int p = idx >> 5, oc = idx & 31;
        float v = s_c3[p*33 + oc] + s_c3[(16+p)*33 + oc] + __ldg(b3 + oc);
        g_h3[f*512 + oc*16 + p] = fmaxf(v, 0.f);
    }
}

// ---------------- chunked 3xTF32 GEMM (fc1, K=512) ----------------
__global__ void __launch_bounds__(256) k_tc(
    const float* __restrict__ A, int lda,
    const float* __restrict__ W, int ldw,
    const float* __restrict__ bias,
    float* __restrict__ C, int ldc, int K, int ep)
{
    __shared__ float sA[32][72];
    __shared__ float sW[32][136];

    const int tid = threadIdx.x;
    const int warpid = tid >> 5, lane = tid & 31;
    const int g = lane >> 2, tig = lane & 3;
    const int wm = warpid >> 2, wn = warpid & 3;
    const int mtile = blockIdx.y, ntile = blockIdx.x;

    const int arow0 = tid & 63, akq0 = tid >> 6;
    const int akq1 = akq0 + 4;
    const float* Abase0 = A + (mtile*64 + arow0)*lda + akq0*4;
    const float* Abase1 = A + (mtile*64 + arow0)*lda + akq1*4;

    float acc[2][4][4];
    #pragma unroll
    for (int mi = 0; mi < 2; mi++)
        #pragma unroll
        for (int ni = 0; ni < 4; ni++)
            #pragma unroll
            for (int q = 0; q < 4; q++) acc[mi][ni][q] = 0.f;

    const int nkc = K >> 5;
    float4 pa0 = *(const float4*)(Abase0);
    float4 pa1 = *(const float4*)(Abase1);
    float4 pw[4];
    #pragma unroll
    for (int q = 0; q < 4; q++) {
        int idx = tid + q*256;
        int n = idx & 127, kq = idx >> 7;
        pw[q] = *(const float4*)(W + (ntile*128 + n)*ldw + kq*4);
    }

    for (int kt = 0; kt < nkc; kt++) {
        sA[akq0*4+0][arow0] = pa0.x; sA[akq0*4+1][arow0] = pa0.y;
        sA[akq0*4+2][arow0] = pa0.z; sA[akq0*4+3][arow0] = pa0.w;
        sA[akq1*4+0][arow0] = pa1.x; sA[akq1*4+1][arow0] = pa1.y;
        sA[akq1*4+2][arow0] = pa1.z; sA[akq1*4+3][arow0] = pa1.w;
        #pragma unroll
        for (int q = 0; q < 4; q++) {
            int idx = tid + q*256;
            int n = idx & 127, kq = idx >> 7;
            sW[kq*4+0][n] = pw[q].x; sW[kq*4+1][n] = pw[q].y;
            sW[kq*4+2][n] = pw[q].z; sW[kq*4+3][n] = pw[q].w;
        }
        __syncthreads();

        if (kt + 1 < nkc) {
            int kb = (kt+1) << 5;
            pa0 = *(const float4*)(Abase0 + kb);
            pa1 = *(const float4*)(Abase1 + kb);
            #pragma unroll
            for (int q = 0; q < 4; q++) {
                int idx = tid + q*256;
                int n = idx & 127, kq = idx >> 7;
                pw[q] = *(const float4*)(W + (ntile*128 + n)*ldw + kb + kq*4);
            }
        }

        #pragma unroll
        for (int kk = 0; kk < 4; kk++) {
            const int k0 = kk*8 + tig, k1 = k0 + 4;
            unsigned ahi[2][4], alo[2][4], bhi[4][2], blo[4][2];
            #pragma unroll
            for (int mi = 0; mi < 2; mi++) {
                int r0 = wm*32 + mi*16 + g;
                split2(sA[k0][r0],    ahi[mi][0], alo[mi][0]);
                split2(sA[k0][r0+8],  ahi[mi][1], alo[mi][1]);
                split2(sA[k1][r0],    ahi[mi][2], alo[mi][2]);
                split2(sA[k1][r0+8],  ahi[mi][3], alo[mi][3]);
            }
            #pragma unroll
            for (int ni = 0; ni < 4; ni++) {
                int c0 = wn*32 + ni*8 + g;
                split2(sW[k0][c0], bhi[ni][0], blo[ni][0]);
                split2(sW[k1][c0], bhi[ni][1], blo[ni][1]);
            }
            #pragma unroll
            for (int mi = 0; mi < 2; mi++)
                #pragma unroll
                for (int ni = 0; ni < 4; ni++) {
                    mma8(acc[mi][ni], ahi[mi], bhi[ni]);
                    mma8(acc[mi][ni], alo[mi], bhi[ni]);
                    mma8(acc[mi][ni], ahi[mi], blo[ni]);
                }
        }
        __syncthreads();
    }

    #pragma unroll
    for (int mi = 0; mi < 2; mi++) {
        #pragma unroll
        for (int ni = 0; ni < 4; ni++) {
            int row0 = mtile*64 + wm*32 + mi*16 + g;
            int col0 = ntile*128 + wn*32 + ni*8 + 2*tig;
            float v0 = acc[mi][ni][0], v1 = acc[mi][ni][1];
            float v2 = acc[mi][ni][2], v3 = acc[mi][ni][3];
            if (ep >= 1) {
                float b0 = bias[col0], b1 = bias[col0+1];
                v0 += b0; v1 += b1; v2 += b0; v3 += b1;
            }
            if (ep == 2) {
                v0 = fmaxf(v0, 0.f); v1 = fmaxf(v1, 0.f);
                v2 = fmaxf(v2, 0.f); v3 = fmaxf(v3, 0.f);
            }
            float* p = C + row0*ldc + col0;
            p[0] = v0; p[1] = v1;
            p[8*ldc] = v2; p[8*ldc + 1] = v3;
        }
    }
}

// ---------------- single-stage 3xTF32 GEMM (K=128 per block, cp.async) -------------
#define TCS_SMEM_BYTES ((64*132 + 128*132)*4)

__global__ void __launch_bounds__(256) k_tcs(
    const float* __restrict__ A, int lda,
    const float* __restrict__ W, int ldw,
    const float* __restrict__ bias,
    float* __restrict__ C, int ldc,
    int partStride, int mode, int ep)
{
    extern __shared__ float smem[];
    float* sA = smem;
    float* sW = smem + 64*132;
    const int tid = threadIdx.x;
    const int warpid = tid >> 5, lane = tid & 31;
    const int g = lane >> 2, tig = lane & 3;
    const int wm = warpid >> 2, wn = warpid & 3;
    const int mtile = blockIdx.y, ntile = blockIdx.x, z = blockIdx.z;
    const int kStart = z*128;

    const float* Ab; int abase, ldae;
    if (mode == 1) {
        if (kStart < KSZ) { Ab = g_r;   abase = kStart; }
        else              { Ab = g_hst; abase = kStart - KSZ; }
        ldae = 256;
    } else { Ab = A; abase = kStart; ldae = lda; }
    float* Cp = C + z*partStride;

    #pragma unroll
    for (int q = 0; q < 8; q++) {
        int c = tid + q*256;
        int row = c >> 5, kc = c & 31;
        const float* src = Ab + (mtile*64 + row)*ldae + abase + kc*4;
        cpasync16((unsigned)__cvta_generic_to_shared(sA + row*132 + kc*4), src);
    }
    #pragma unroll
    for (int q = 0; q < 16; q++) {
        int c = tid + q*256;
        int col = c >> 5, kc = c & 31;
        const float* src = W + (ntile*128 + col)*ldw + kStart + kc*4;
        cpasync16((unsigned)__cvta_generic_to_shared(sW + col*132 + kc*4), src);
    }
    asm volatile("cp.async.commit_group;\n");
    asm volatile("cp.async.wait_group 0;\n");
    __syncthreads();

    float acc[2][4][4];
    #pragma unroll
    for (int mi = 0; mi < 2; mi++)
        #pragma unroll
        for (int ni = 0; ni < 4; ni++)
            #pragma unroll
            for (int q = 0; q < 4; q++) acc[mi][ni][q] = 0.f;

    #pragma unroll 2
    for (int kk = 0; kk < 16; kk++) {
        const int k0 = kk*8 + tig, k1 = k0 + 4;
        unsigned ahi[2][4], alo[2][4], bhi[4][2], blo[4][2];
        #pragma unroll
        for (int mi = 0; mi < 2; mi++) {
            const float* r0 = sA + (wm*32 + mi*16 + g)*132;
            const float* r1 = r0 + 8*132;
            split2(r0[k0], ahi[mi][0], alo[mi][0]);
            split2(r1[k0], ahi[mi][1], alo[mi][1]);
            split2(r0[k1], ahi[mi][2], alo[mi][2]);
            split2(r1[k1], ahi[mi][3], alo[mi][3]);
        }
        #pragma unroll
        for (int ni = 0; ni < 4; ni++) {
            const float* c0 = sW + (wn*32 + ni*8 + g)*132;
            split2(c0[k0], bhi[ni][0], blo[ni][0]);
            split2(c0[k1], bhi[ni][1], blo[ni][1]);
        }
        #pragma unroll
        for (int mi = 0; mi < 2; mi++)
            #pragma unroll
            for (int ni = 0; ni < 4; ni++) {
                mma8(acc[mi][ni], ahi[mi], bhi[ni]);
                mma8(acc[mi][ni], alo[mi], bhi[ni]);
                mma8(acc[mi][ni], ahi[mi], blo[ni]);
            }
    }

    #pragma unroll
    for (int mi = 0; mi < 2; mi++) {
        #pragma unroll
        for (int ni = 0; ni < 4; ni++) {
            int row0 = mtile*64 + wm*32 + mi*16 + g;
            int col0 = ntile*128 + wn*32 + ni*8 + 2*tig;
            float v0 = acc[mi][ni][0], v1 = acc[mi][ni][1];
            float v2 = acc[mi][ni][2], v3 = acc[mi][ni][3];
            if (ep >= 1) {
                float b0 = bias[col0], b1 = bias[col0+1];
                v0 += b0; v1 += b1; v2 += b0; v3 += b1;
            }
            float* p = Cp + row0*ldc + col0;
            p[0] = v0; p[1] = v1;
            p[8*ldc] = v2; p[8*ldc + 1] = v3;
        }
    }
}

// ---------------- context norm over time, fused fc2 combine + bias + relu ------------
__global__ void k_ctxnorm(const float* __restrict__ fc2b,
                          const float* __restrict__ gamma, const float* __restrict__ beta)
{
    int b = blockIdx.x, d = threadIdx.x;
    float bias = fc2b[d];
    float v[TT];
    float s = 0.f, s2 = 0.f;
    #pragma unroll
    for (int t = 0; t < TT; t++) {
        int idx = (b*TT+t)*DD + d;
        v[t] = fmaxf(g_fc2p[idx] + g_fc2p[NFRM*DD + idx] + bias, 0.f);
        s += v[t]; s2 += v[t]*v[t];
    }
    float mu  = s / TT;
    float var = (s2 - TT*mu*mu) / (TT - 1);
    float inv = 1.f / sqrtf(var + EPSF);
    float ga = gamma[d], be = beta[d];
    #pragma unroll
    for (int t = 0; t < TT; t++)
        g_z[(b*TT+t)*DD + d] = (v[t] - mu)*inv*ga + be;
}

// ---------------- setup (grid MUST cover BB*MEMN*KSZ = 1,310,720 threads) -----------
__global__ void k_setup(const float* __restrict__ mem0,
                        const float* __restrict__ wi, const float* __restrict__ wh,
                        const float* __restrict__ wk, const float* __restrict__ wwk,
                        const float* __restrict__ wv,
                        const float* __restrict__ w2, const float* __restrict__ w3,
                        float* __restrict__ out, int out_size)
{
    int i = blockIdx.x*256 + threadIdx.x;
    if (i < BB*MEMN*KSZ) g_M[i] = mem0[i % (MEMN*KSZ)];
    if (i < 4*BB*1024) g_gates4[i] = 0.f;    // exact: t=0 gates launch is skipped
    if (i < 1024*512) {
        int j = i >> 9, c = i & 511;
        g_Wcat[i] = (c < 256) ? wi[j*384 + 128 + c] : wh[j*256 + (c-256)];
    }
    if (i < 1024*128) {
        int j = i >> 7, c = i & 127;
        g_Wz[i] = wi[j*384 + c];
    }
    if (i < 768*256) {
        int n = i >> 8;
        g_Whead[i] = (n < 256) ? wk[i] : ((n < 512) ? wwk[i - 256*256] : wv[i - 512*256]);
    }
    if (i < 16384) {
        int lane = i & 31;
        int j = i >> 5;
        int n8i = j & 3; j >>= 2;
        int half = j & 1; j >>= 1;
        int ick = j & 3;
        int khw = j >> 2;
        int n = n8i*8 + (lane >> 2);
        int kic = ick*8 + (lane & 3) + half*4;
        g_w2r[i] = w2[n*512 + kic*16 + khw];
        g_w3r[i] = w3[n*512 + kic*16 + khw];
    }
    if (i < BB*HH) { g_hst[i] = 0.f; g_cst[i] = 0.f; }
    if (i < BB*KSZ) g_r[i] = 0.f;
    if (i < out_size) out[i] = 0.f;
}

// ---------------- per-step: LSTM update (sums gz + np gate partials, float4) ---------
__global__ void k_lstm(int t, int np)
{
    int idx = blockIdx.x*256 + threadIdx.x;
    int b = idx >> 6, j = (idx & 63) << 2;
    const float* gz = g_gz + (b*TT + t)*1024;
    float4 g[4];
    #pragma unroll
    for (int gt = 0; gt < 4; gt++) g[gt] = *(const float4*)(gz + gt*256 + j);
    for (int z = 0; z < np; z++) {
        const float* gp = g_gates4 + z*(BB*1024) + b*1024;
        #pragma unroll
        for (int gt = 0; gt < 4; gt++) {
            float4 p = *(const float4*)(gp + gt*256 + j);
            g[gt].x += p.x; g[gt].y += p.y; g[gt].z += p.z; g[gt].w += p.w;
        }
    }
    float4 c = *(const float4*)(g_cst + b*HH + j);
    float4 cn, hn;
    cn.x = sigmf(g[1].x)*c.x + sigmf(g[0].x)*tanhf(g[2].x);
    cn.y = sigmf(g[1].y)*c.y + sigmf(g[0].y)*tanhf(g[2].y);
    cn.z = sigmf(g[1].z)*c.z + sigmf(g[0].z)*tanhf(g[2].z);
    cn.w = sigmf(g[1].w)*c.w + sigmf(g[0].w)*tanhf(g[2].w);
    hn.x = sigmf(g[3].x)*tanhf(cn.x);
    hn.y = sigmf(g[3].y)*tanhf(cn.y);
    hn.z = sigmf(g[3].z)*tanhf(cn.z);
    hn.w = sigmf(g[3].w)*tanhf(cn.w);
    *(float4*)(g_cst + b*HH + j) = cn;
    *(float4*)(g_hst + b*HH + j) = hn;
}

// ---------------- per-step: memory read/write + (last step) output ----------------
__global__ void __launch_bounds__(256) k_mem(int t, const float* __restrict__ wo,
                                             const float* __restrict__ wob,
                                             float* __restrict__ out, int out_size)
{
    __shared__ float s_kr[256], s_kw[256], s_rnew[256];
    __shared__ float s_simr[MEMN], s_simw[MEMN];
    __shared__ float s_wr[4], s_ws[4];
    __shared__ int   s_ir[4], s_iw[4];
    __shared__ float s_red[16];
    __shared__ float s_nrm[2];
    __shared__ float s_y[4];

    int b = blockIdx.x, tid = threadIdx.x;
    int lane = tid & 31, wid = tid >> 5;

    float kr = 0.f, kw = 0.f, vvs = 0.f;
    #pragma unroll
    for (int z = 0; z < 2; z++) {
        const float* hp = g_hpart + z*(BB*768) + b*768;
        kr  += hp[tid];
        kw  += hp[256 + tid];
        vvs += hp[512 + tid];
    }
    float vv = tanhf(vvs);
    s_kr[tid] = kr;
    s_kw[tid] = kw;

    float pr = kr*kr, pw = kw*kw;
    #pragma unroll
    for (int o = 16; o > 0; o >>= 1) {
        pr += __shfl_xor_sync(0xffffffffu, pr, o);
        pw += __shfl_xor_sync(0xffffffffu, pw, o);
    }
    if (lane == 0) { s_red[wid] = pr; s_red[8 + wid] = pw; }
    __syncthreads();
    if (tid == 0) {
        float sr = 0.f, sw = 0.f;
        #pragma unroll
        for (int w = 0; w < 8; w++) { sr += s_red[w]; sw += s_red[8 + w]; }
        s_nrm[0] = 1.f / (sqrtf(sr) + EPSF);
        s_nrm[1] = 1.f / (sqrtf(sw) + EPSF);
    }
    __syncthreads();

    for (int n = wid; n < MEMN; n += 8) {
        const float* Mr = g_M + (b*MEMN + n)*KSZ;
        float dr = 0.f, dw = 0.f, nn = 0.f;
        #pragma unroll
        for (int d0 = 0; d0 < KSZ; d0 += 32) {
            float m = Mr[d0 + lane];
            dr += s_kr[d0 + lane]*m;
            dw += s_kw[d0 + lane]*m;
            nn += m*m;
        }
        #pragma unroll
        for (int o = 16; o > 0; o >>= 1) {
            dr += __shfl_xor_sync(0xffffffffu, dr, o);
            dw += __shfl_xor_sync(0xffffffffu, dw, o);
            nn += __shfl_xor_sync(0xffffffffu, nn, o);
        }
        if (lane == 0) {
            float mi = 1.f / (sqrtf(nn) + EPSF);
            s_simr[n] = dr * s_nrm[0] * mi;
            s_simw[n] = dw * s_nrm[1] * mi;
        }
    }
    __syncthreads();

    if (tid < 2) {
        const float* sims = tid ? s_simw : s_simr;
        float* wout = tid ? s_ws : s_wr;
        int*   iout = tid ? s_iw : s_ir;
        unsigned used = 0;
        float vals[4];
        #pragma unroll
        for (int k = 0; k < 4; k++) {
            float best = -1e30f; int bi = 0;
            for (int n = 0; n < MEMN; n++) {
                if (!((used >> n) & 1u) && sims[n] > best) { best = sims[n]; bi = n; }
            }
            used |= 1u << bi;
            iout[k] = bi; vals[k] = best;
        }
        float mx = vals[0], ssum = 0.f, e[4];
        #pragma unroll
        for (int k = 0; k < 4; k++) { e[k] = expf(vals[k] - mx); ssum += e[k]; }
        #pragma unroll
        for (int k = 0; k < 4; k++) wout[k] = e[k] / ssum;
    }
    __syncthreads();

    float r = 0.f;
    #pragma unroll
    for (int k = 0; k < 4; k++)
        r += s_wr[k] * g_M[(b*MEMN + s_ir[k])*KSZ + tid];
    g_r[b*KSZ + tid] = r;
    s_rnew[tid] = r;

    #pragma unroll
    for (int k = 0; k < 4; k++)
        g_M[(b*MEMN + s_iw[k])*KSZ + tid] += s_ws[k] * vv;

    if (t == TT - 1) {
        __syncthreads();
        if (wid < 4) {
            const float* wrow = wo + wid*512;
            float p = 0.f;
            for (int j = lane; j < 256; j += 32) p += wrow[j]       * g_hst[b*HH + j];
            for (int j = lane; j < 256; j += 32) p += wrow[256 + j] * s_rnew[j];
            #pragma unroll
            for (int o = 16; o > 0; o >>= 1) p += __shfl_xor_sync(0xffffffffu, p, o);
            if (lane == 0) s_y[wid] = p + wob[wid];
        }
        __syncthreads();
        if (tid < 4 && (b*4 + tid) < out_size) out[b*4 + tid] = s_y[tid];
        if (tid == 0 && out_size >= BB*YY + BB) {
            int am = 0; float bv = s_y[0];
            #pragma unroll
            for (int o = 1; o < 4; o++) if (s_y[o] > bv) { bv = s_y[o]; am = o; }
            out[BB*YY + b] = (float)am;
        }
    }
}

// ---------------- launch ----------------
extern "C" void kernel_launch(void* const* d_in, const int* in_sizes, int n_in,
                              void* d_out, int out_size)
{
    const float* x    = (const float*)d_in[0];
    const float* c1w  = (const float*)d_in[1];
    const float* c1b  = (const float*)d_in[2];
    const float* c2w  = (const float*)d_in[3];
    const float* c2b  = (const float*)d_in[4];
    const float* c3w  = (const float*)d_in[5];
    const float* c3b  = (const float*)d_in[6];
    const float* fc1w = (const float*)d_in[7];
    const float* fc1b = (const float*)d_in[8];
    const float* fc2w = (const float*)d_in[9];
    const float* fc2b = (const float*)d_in[10];
    const float* gamma= (const float*)d_in[11];
    const float* beta = (const float*)d_in[12];
    const float* lwi  = (const float*)d_in[13];
    const float* lwh  = (const float*)d_in[14];
    const float* lb   = (const float*)d_in[15];
    const float* wk   = (const float*)d_in[16];
    const float* wwk  = (const float*)d_in[17];
    const float* wv   = (const float*)d_in[18];
    const float* wo   = (const float*)d_in[19];
    const float* wob  = (const float*)d_in[20];
    const float* mem0 = (const float*)d_in[21];
    float* out = (float*)d_out;

    cudaFuncSetAttribute(k_convf, cudaFuncAttributeMaxDynamicSharedMemorySize,
                         CONVF_SMEM_FLOATS * 4);
    cudaFuncSetAttribute(k_tcs, cudaFuncAttributeMaxDynamicSharedMemorySize,
                         TCS_SMEM_BYTES);

    float *p_h3, *p_fc1, *p_fc2p, *p_z, *p_gz, *p_g4, *p_hp, *p_h;
    float *p_wcat, *p_wz, *p_whead, *p_w2r, *p_w3r;
    cudaGetSymbolAddress((void**)&p_h3,    g_h3);
    cudaGetSymbolAddress((void**)&p_fc1,   g_fc1);
    cudaGetSymbolAddress((void**)&p_fc2p,  g_fc2p);
    cudaGetSymbolAddress((void**)&p_z,     g_z);
    cudaGetSymbolAddress((void**)&p_gz,    g_gz);
    cudaGetSymbolAddress((void**)&p_g4,    g_gates4);
    cudaGetSymbolAddress((void**)&p_hp,    g_hpart);
    cudaGetSymbolAddress((void**)&p_h,     g_hst);
    cudaGetSymbolAddress((void**)&p_wcat,  g_Wcat);
    cudaGetSymbolAddress((void**)&p_wz,    g_Wz);
    cudaGetSymbolAddress((void**)&p_whead, g_Whead);
    cudaGetSymbolAddress((void**)&p_w2r,   g_w2r);
    cudaGetSymbolAddress((void**)&p_w3r,   g_w3r);

    // grid sized for the LARGEST init target: g_M (BB*MEMN*KSZ = 1,310,720)
    k_setup<<<(BB*MEMN*KSZ + 255)/256, 256>>>(mem0, lwi, lwh, wk, wwk, wv,
                                              c2w, c3w, out, out_size);

    // encoder (tensor-core conv)
    k_convf<<<NFRM, 256, CONVF_SMEM_FLOATS * 4>>>(x, c1w, c1b, p_w2r, c2b, p_w3r, c3b);
    // fc1 (chunked, K=512)
    k_tc<<<dim3(2, 80), 256>>>(p_h3, 512, fc1w, 512, fc1b, p_fc1, 256, 512, 2);
    // fc2: split-K x2 partials; combine in ctxnorm
    k_tcs<<<dim3(1, 80, 2), 256, TCS_SMEM_BYTES>>>(p_fc1, 256, fc2w, 256, nullptr,
                                                   p_fc2p, 128, NFRM*DD, 0, 0);
    k_ctxnorm<<<BB, 128>>>(fc2b, gamma, beta);
    // Gz = z @ Wz^T + lstm_b (single-stage, K=128)
    k_tcs<<<dim3(8, 80, 1), 256, TCS_SMEM_BYTES>>>(p_z, 128, p_wz, 128, lb,
                                                   p_gz, 1024, 0, 0, 1);

    for (int t = 0; t < TT; t++) {
        // gates: [r|h] @ Wcat^T, split-K x4, single-stage.
        // t=0: r=h=0 -> all partials exactly zero (pre-zeroed); skip launch.
        if (t > 0)
            k_tcs<<<dim3(8, 4, 4), 256, TCS_SMEM_BYTES>>>(nullptr, 0, p_wcat, 512,
                                                          nullptr, p_g4, 1024,
                                                          BB*1024, 1, 0);
        k_lstm<<<64, 256>>>(t, (t > 0) ? 4 : 0);
        // heads: h @ Whead^T, split-K x2, single-stage
        k_tcs<<<dim3(6, 4, 2), 256, TCS_SMEM_BYTES>>>(p_h, 256, p_whead, 256, nullptr,
                                                      p_hp, 768, BB*768, 0, 0);
        k_mem<<<BB, 256>>>(t, wo, wob, out, out_size);
    }
}